// round 1
// baseline (speedup 1.0000x reference)
#include <cuda_runtime.h>
#include <cuda_fp16.h>
#include <cstdint>

#define NROW 4096
#define IND  128
#define OD   64
#define NH   4
#define NC   80          // padded hv cols: 64 h | col64 = 1.0 | 65..79 = 0
#define HS_STRIDE 88     // smem stride (halves) for hv tile
#define KC   64          // k-chunk (columns m per iteration)
#define RT   128         // row tile per block
#define ALPHAV 0.2f
#define NW   (NROW/32)   // adj bit words per row = 128

// ---------------- scratch (static device globals; no cudaMalloc) ----------------
__device__ float    g_h[NH*NROW*OD];        // 4 MB
__device__ __half   g_hv[NH*NROW*NC];       // 2.6 MB  (h fp16 + ones col + pad)
__device__ float    g_negc[NH*NROW];        // -c_n
__device__ float    g_t[NH*NROW];           // t_m
__device__ __half2  g_uv[NH*NROW];          // (e^t, e^{0.2 t})
__device__ __half2  g_e12[NH*NROW];         // (e^c, e^{0.2 c})
__device__ uint32_t g_adjbits[NROW*NW];     // 2 MB bit-packed adjacency

// ---------------- helpers ----------------
__device__ __forceinline__ uint32_t smem_u32(const void* p) {
    return (uint32_t)__cvta_generic_to_shared(p);
}
__device__ __forceinline__ void ldm_x4(uint32_t& r0, uint32_t& r1, uint32_t& r2, uint32_t& r3, uint32_t addr) {
    asm volatile("ldmatrix.sync.aligned.m8n8.x4.shared.b16 {%0,%1,%2,%3}, [%4];"
                 : "=r"(r0), "=r"(r1), "=r"(r2), "=r"(r3) : "r"(addr));
}
__device__ __forceinline__ void ldm_x4_t(uint32_t& r0, uint32_t& r1, uint32_t& r2, uint32_t& r3, uint32_t addr) {
    asm volatile("ldmatrix.sync.aligned.m8n8.x4.trans.shared.b16 {%0,%1,%2,%3}, [%4];"
                 : "=r"(r0), "=r"(r1), "=r"(r2), "=r"(r3) : "r"(addr));
}
__device__ __forceinline__ void mma16816(float* c, const uint32_t* a, const uint32_t* b) {
    asm volatile("mma.sync.aligned.m16n8k16.row.col.f32.f16.f16.f32 "
                 "{%0,%1,%2,%3}, {%4,%5,%6,%7}, {%8,%9}, {%0,%1,%2,%3};"
                 : "+f"(c[0]), "+f"(c[1]), "+f"(c[2]), "+f"(c[3])
                 : "r"(a[0]), "r"(a[1]), "r"(a[2]), "r"(a[3]), "r"(b[0]), "r"(b[1]));
}

// ---------------- K1: h = x @ W per head; also write hv fp16 (+ ones col) ----------------
__global__ __launch_bounds__(256) void k1_proj(const float* __restrict__ x,
                                               const float* __restrict__ W) {
    __shared__ float xs[64][65];
    __shared__ float ws[64][65];
    int head = blockIdx.y;
    int r0 = blockIdx.x * 64;
    int tid = threadIdx.x;
    int tx = tid & 15, ty = tid >> 4;
    float acc[4][4] = {};
    for (int k0 = 0; k0 < IND; k0 += 64) {
        for (int idx = tid; idx < 64 * 64; idx += 256) {
            int r = idx >> 6, c = idx & 63;
            xs[r][c] = x[(r0 + r) * IND + k0 + c];
            ws[r][c] = W[head * IND * OD + (k0 + r) * OD + c];
        }
        __syncthreads();
        for (int k = 0; k < 64; k++) {
            float wv[4];
            #pragma unroll
            for (int j = 0; j < 4; j++) wv[j] = ws[k][tx * 4 + j];
            #pragma unroll
            for (int i = 0; i < 4; i++) {
                float xv = xs[ty + 16 * i][k];
                #pragma unroll
                for (int j = 0; j < 4; j++) acc[i][j] += xv * wv[j];
            }
        }
        __syncthreads();
    }
    #pragma unroll
    for (int i = 0; i < 4; i++)
        #pragma unroll
        for (int j = 0; j < 4; j++) {
            int r = r0 + ty + 16 * i, c = tx * 4 + j;
            g_h[(head * NROW + r) * OD + c] = acc[i][j];
            g_hv[(head * NROW + r) * NC + c] = __float2half(acc[i][j]);
        }
    // pad columns: col 64 = 1.0 (row-sum column -> softmax denominator), 65..79 = 0
    for (int idx = tid; idx < 64 * 16; idx += 256) {
        int r = idx >> 4, pc = idx & 15;
        g_hv[(head * NROW + r0 + r) * NC + 64 + pc] =
            (pc == 0) ? __float2half(1.0f) : __float2half(0.0f);
    }
}

// ---------------- K2: per (head,n): c = h.a_self, t = h.a_neigh; pack exps ----------------
__global__ __launch_bounds__(256) void k2_scores(const float* __restrict__ a_self,
                                                 const float* __restrict__ a_neigh) {
    int head = blockIdx.y;
    int n = blockIdx.x * 8 + (threadIdx.x >> 5);
    int lane = threadIdx.x & 31;
    const float2* hp = (const float2*)&g_h[(head * NROW + n) * OD];
    float2 hv = hp[lane];
    float2 asv = ((const float2*)(a_self + head * OD))[lane];
    float2 anv = ((const float2*)(a_neigh + head * OD))[lane];
    float ps = hv.x * asv.x + hv.y * asv.y;
    float pn = hv.x * anv.x + hv.y * anv.y;
    #pragma unroll
    for (int o = 16; o > 0; o >>= 1) {
        ps += __shfl_xor_sync(0xffffffffu, ps, o);
        pn += __shfl_xor_sync(0xffffffffu, pn, o);
    }
    if (lane == 0) {
        float c = ps, t = pn;
        g_negc[head * NROW + n] = -c;
        g_t[head * NROW + n] = t;
        g_uv[head * NROW + n]  = __floats2half2_rn(expf(t), expf(ALPHAV * t));
        g_e12[head * NROW + n] = __floats2half2_rn(expf(c), expf(ALPHAV * c));
    }
}

// ---------------- K3: bit-pack adjacency ----------------
__global__ __launch_bounds__(128) void k3_bits(const float* __restrict__ adj) {
    int n = blockIdx.x;
    int lane = threadIdx.x & 31;
    int w0 = threadIdx.x >> 5;
    for (int w = w0; w < NW; w += 4) {
        float v = adj[n * NROW + w * 32 + lane];
        unsigned m = __ballot_sync(0xffffffffu, v != 0.0f);
        if (lane == 0) g_adjbits[n * NW + w] = m;
    }
}

// ---------------- K4: fused P-build + tensor-core P@hv + normalize ----------------
__global__ __launch_bounds__(256) void k4_main(float* __restrict__ out) {
    __shared__ __align__(16) __half2 Ps[RT][36];        // P tile, stride 72 halves (144B)
    __shared__ __align__(16) __half  Hs[KC][HS_STRIDE]; // hv tile, stride 88 halves (176B)
    __shared__ float   ts[KC];
    __shared__ __half2 uvs[KC];
    __shared__ float   dRow[RT];

    int head = blockIdx.y;
    int n0 = blockIdx.x * RT;
    int tid = threadIdx.x;
    int lane = tid & 31, wid = tid >> 5;
    int warp_m = wid >> 1;            // 0..3 -> rows warp_m*32
    int warp_n = (wid & 1) * 40;      // 0 or 40

    // per-thread P-build row constants (row fixed for the whole kernel)
    int pr = tid >> 1;                // 0..127
    int mh = tid & 1;                 // which 32-wide m half of the 64 chunk
    float   negc = g_negc[head * NROW + n0 + pr];
    __half2 e12  = g_e12[head * NROW + n0 + pr];

    float acc[2][5][4];
    #pragma unroll
    for (int a = 0; a < 2; a++)
        #pragma unroll
        for (int b = 0; b < 5; b++)
            #pragma unroll
            for (int c = 0; c < 4; c++) acc[a][b][c] = 0.0f;

    const uint32_t* hv32 = (const uint32_t*)&g_hv[head * NROW * NC];

    for (int kb = 0; kb < NROW / KC; kb++) {
        int m0 = kb * KC;
        // load hv tile (64 x 80 halves = 2560 u32)
        #pragma unroll
        for (int i = 0; i < 10; i++) {
            int idx = tid + i * 256;
            int r = idx / 40, cg = idx % 40;
            ((uint32_t*)&Hs[r][0])[cg] = hv32[(m0 + r) * 40 + cg];
        }
        if (tid < KC) {
            ts[tid]  = g_t[head * NROW + m0 + tid];
            uvs[tid] = g_uv[head * NROW + m0 + tid];
        }
        __syncthreads();

        // build P tile: P[n,m] = adj ? (c+t>0 ? e^c e^t : e^{ac} e^{at}) : 0
        {
            uint32_t bits = g_adjbits[(n0 + pr) * NW + kb * 2 + mh];
            int base = mh * 32;
            #pragma unroll
            for (int j = 0; j < 32; j += 2) {
                __half2 p0 = __hmul2(uvs[base + j],     e12);  // (E1*u, E2*v)
                __half2 p1 = __hmul2(uvs[base + j + 1], e12);
                __half w0 = (ts[base + j]     > negc) ? __low2half(p0) : __high2half(p0);
                __half w1 = (ts[base + j + 1] > negc) ? __low2half(p1) : __high2half(p1);
                if (!((bits >> j) & 1u))       w0 = __ushort_as_half((unsigned short)0);
                if (!((bits >> (j + 1)) & 1u)) w1 = __ushort_as_half((unsigned short)0);
                Ps[pr][(base + j) >> 1] = __halves2half2(w0, w1);
            }
        }
        __syncthreads();

        // tensor-core accumulate: C[128x80] += P[128x64] @ Hs[64x80]
        const char* PsB = (const char*)Ps;
        const char* HsB = (const char*)Hs;
        #pragma unroll
        for (int kk = 0; kk < 4; kk++) {
            uint32_t a[2][4];
            #pragma unroll
            for (int mt = 0; mt < 2; mt++) {
                uint32_t addr = smem_u32(PsB + (warp_m * 32 + mt * 16 + (lane & 15)) * 144
                                             + (kk * 16 + (lane >> 4) * 8) * 2);
                ldm_x4(a[mt][0], a[mt][1], a[mt][2], a[mt][3], addr);
            }
            uint32_t b[6][2];
            #pragma unroll
            for (int gg = 0; gg < 3; gg++) {
                uint32_t addr = smem_u32(HsB + (kk * 16 + (lane & 15)) * (HS_STRIDE * 2)
                                             + (warp_n + gg * 16 + (lane >> 4) * 8) * 2);
                ldm_x4_t(b[2 * gg][0], b[2 * gg][1], b[2 * gg + 1][0], b[2 * gg + 1][1], addr);
            }
            #pragma unroll
            for (int mt = 0; mt < 2; mt++)
                #pragma unroll
                for (int nt = 0; nt < 5; nt++)
                    mma16816(&acc[mt][nt][0], &a[mt][0], &b[nt][0]);
        }
        __syncthreads();
    }

    // exchange denominators (global col 64 lives in odd warps, nt=3, t4==0)
    int g = lane >> 2, t4 = lane & 3;
    if ((wid & 1) == 1 && t4 == 0) {
        #pragma unroll
        for (int mt = 0; mt < 2; mt++) {
            dRow[warp_m * 32 + mt * 16 + g]     = acc[mt][3][0];
            dRow[warp_m * 32 + mt * 16 + 8 + g] = acc[mt][3][2];
        }
    }
    __syncthreads();

    // normalize + write out[n][head*64 + col]
    #pragma unroll
    for (int mt = 0; mt < 2; mt++) {
        int lr0 = warp_m * 32 + mt * 16 + g;
        float inv0 = 1.0f / dRow[lr0];
        float inv1 = 1.0f / dRow[lr0 + 8];
        int row0 = n0 + lr0;
        #pragma unroll
        for (int nt = 0; nt < 5; nt++) {
            int col = warp_n + nt * 8 + 2 * t4;
            if (col < 64) {
                float* o0 = &out[row0 * (NH * OD) + head * OD + col];
                o0[0] = acc[mt][nt][0] * inv0;
                o0[1] = acc[mt][nt][1] * inv0;
                float* o1 = &out[(row0 + 8) * (NH * OD) + head * OD + col];
                o1[0] = acc[mt][nt][2] * inv1;
                o1[1] = acc[mt][nt][3] * inv1;
            }
        }
    }
}

// ---------------- launch ----------------
extern "C" void kernel_launch(void* const* d_in, const int* in_sizes, int n_in,
                              void* d_out, int out_size) {
    const float* x       = (const float*)d_in[0];
    const float* adj     = (const float*)d_in[1];
    const float* W       = (const float*)d_in[2];
    const float* a_self  = (const float*)d_in[3];
    const float* a_neigh = (const float*)d_in[4];
    float* out = (float*)d_out;

    k1_proj  <<<dim3(NROW / 64, NH), 256>>>(x, W);
    k2_scores<<<dim3(NROW / 8,  NH), 256>>>(a_self, a_neigh);
    k3_bits  <<<NROW, 128>>>(adj);
    k4_main  <<<dim3(NROW / RT, NH), 256>>>(out);
}

// round 2
// speedup vs baseline: 1.2770x; 1.2770x over previous
#include <cuda_runtime.h>
#include <cuda_fp16.h>
#include <cstdint>

#define NROW 4096
#define IND  128
#define OD   64
#define NH   4
#define NC   80          // padded hv cols: 64 h | col64 = 1.0 | 65..79 = 0
#define HS_STRIDE 88     // smem stride (halves) for hv tile
#define KC   64          // k-chunk (columns m per iteration)
#define RT   64          // row tile per block
#define NITER (NROW/KC)
#define ALPHAV 0.2f
#define NW   (NROW/32)   // adj bit words per row = 128

// ---------------- scratch (static device globals; no cudaMalloc) ----------------
__device__ float    g_h[NH*NROW*OD];        // 4 MB
__device__ __half   g_hv[NH*NROW*NC];       // 2.6 MB  (h fp16 + ones col + pad)
__device__ __half   g_u[NH*NROW];           // e^t
__device__ __half   g_v[NH*NROW];           // e^{0.2 t}
__device__ __half   g_th[NH*NROW];          // t (half)
__device__ __half2  g_e1[NH*NROW];          // (e^c, e^c)
__device__ __half2  g_e2[NH*NROW];          // (e^{0.2c}, e^{0.2c})
__device__ __half2  g_nc[NH*NROW];          // (-c, -c)
__device__ uint32_t g_adjbits[NROW*NW];     // 2 MB bit-packed adjacency

// ---------------- helpers ----------------
__device__ __forceinline__ uint32_t smem_u32(const void* p) {
    return (uint32_t)__cvta_generic_to_shared(p);
}
__device__ __forceinline__ void ldm_x4(uint32_t& r0, uint32_t& r1, uint32_t& r2, uint32_t& r3, uint32_t addr) {
    asm volatile("ldmatrix.sync.aligned.m8n8.x4.shared.b16 {%0,%1,%2,%3}, [%4];"
                 : "=r"(r0), "=r"(r1), "=r"(r2), "=r"(r3) : "r"(addr));
}
__device__ __forceinline__ void ldm_x4_t(uint32_t& r0, uint32_t& r1, uint32_t& r2, uint32_t& r3, uint32_t addr) {
    asm volatile("ldmatrix.sync.aligned.m8n8.x4.trans.shared.b16 {%0,%1,%2,%3}, [%4];"
                 : "=r"(r0), "=r"(r1), "=r"(r2), "=r"(r3) : "r"(addr));
}
__device__ __forceinline__ void mma16816(float* c, const uint32_t* a, const uint32_t* b) {
    asm volatile("mma.sync.aligned.m16n8k16.row.col.f32.f16.f16.f32 "
                 "{%0,%1,%2,%3}, {%4,%5,%6,%7}, {%8,%9}, {%0,%1,%2,%3};"
                 : "+f"(c[0]), "+f"(c[1]), "+f"(c[2]), "+f"(c[3])
                 : "r"(a[0]), "r"(a[1]), "r"(a[2]), "r"(a[3]), "r"(b[0]), "r"(b[1]));
}
__device__ __forceinline__ void cp16(void* smem_dst, const void* gmem_src) {
    asm volatile("cp.async.cg.shared.global [%0], [%1], 16;"
                 :: "r"(smem_u32(smem_dst)), "l"(gmem_src));
}
__device__ __forceinline__ void cp_commit() {
    asm volatile("cp.async.commit_group;");
}
__device__ __forceinline__ void cp_wait_all() {
    asm volatile("cp.async.wait_group 0;");
}

// ---------------- K1: h = x @ W per head; also write hv fp16 (+ ones col) ----------------
__global__ __launch_bounds__(256) void k1_proj(const float* __restrict__ x,
                                               const float* __restrict__ W) {
    __shared__ float xs[64][65];
    __shared__ float ws[64][65];
    int head = blockIdx.y;
    int r0 = blockIdx.x * 64;
    int tid = threadIdx.x;
    int tx = tid & 15, ty = tid >> 4;
    float acc[4][4] = {};
    for (int k0 = 0; k0 < IND; k0 += 64) {
        for (int idx = tid; idx < 64 * 64; idx += 256) {
            int r = idx >> 6, c = idx & 63;
            xs[r][c] = x[(r0 + r) * IND + k0 + c];
            ws[r][c] = W[head * IND * OD + (k0 + r) * OD + c];
        }
        __syncthreads();
        for (int k = 0; k < 64; k++) {
            float wv[4];
            #pragma unroll
            for (int j = 0; j < 4; j++) wv[j] = ws[k][tx * 4 + j];
            #pragma unroll
            for (int i = 0; i < 4; i++) {
                float xv = xs[ty + 16 * i][k];
                #pragma unroll
                for (int j = 0; j < 4; j++) acc[i][j] += xv * wv[j];
            }
        }
        __syncthreads();
    }
    #pragma unroll
    for (int i = 0; i < 4; i++)
        #pragma unroll
        for (int j = 0; j < 4; j++) {
            int r = r0 + ty + 16 * i, c = tx * 4 + j;
            g_h[(head * NROW + r) * OD + c] = acc[i][j];
            g_hv[(head * NROW + r) * NC + c] = __float2half(acc[i][j]);
        }
    // pad columns: col 64 = 1.0 (row-sum column -> softmax denominator), 65..79 = 0
    for (int idx = tid; idx < 64 * 16; idx += 256) {
        int r = idx >> 4, pc = idx & 15;
        g_hv[(head * NROW + r0 + r) * NC + 64 + pc] =
            (pc == 0) ? __float2half(1.0f) : __float2half(0.0f);
    }
}

// ---------------- K2: per (head,n): c = h.a_self, t = h.a_neigh; pack exps ----------------
__global__ __launch_bounds__(256) void k2_scores(const float* __restrict__ a_self,
                                                 const float* __restrict__ a_neigh) {
    int head = blockIdx.y;
    int n = blockIdx.x * 8 + (threadIdx.x >> 5);
    int lane = threadIdx.x & 31;
    const float2* hp = (const float2*)&g_h[(head * NROW + n) * OD];
    float2 hv = hp[lane];
    float2 asv = ((const float2*)(a_self + head * OD))[lane];
    float2 anv = ((const float2*)(a_neigh + head * OD))[lane];
    float ps = hv.x * asv.x + hv.y * asv.y;
    float pn = hv.x * anv.x + hv.y * anv.y;
    #pragma unroll
    for (int o = 16; o > 0; o >>= 1) {
        ps += __shfl_xor_sync(0xffffffffu, ps, o);
        pn += __shfl_xor_sync(0xffffffffu, pn, o);
    }
    if (lane == 0) {
        float c = ps, t = pn;
        int i = head * NROW + n;
        g_u[i]  = __float2half(expf(t));
        g_v[i]  = __float2half(expf(ALPHAV * t));
        g_th[i] = __float2half(t);
        g_e1[i] = __float2half2_rn(expf(c));
        g_e2[i] = __float2half2_rn(expf(ALPHAV * c));
        g_nc[i] = __float2half2_rn(-c);
    }
}

// ---------------- K3: bit-pack adjacency ----------------
__global__ __launch_bounds__(128) void k3_bits(const float* __restrict__ adj) {
    int n = blockIdx.x;
    int lane = threadIdx.x & 31;
    int w0 = threadIdx.x >> 5;
    for (int w = w0; w < NW; w += 4) {
        float v = adj[n * NROW + w * 32 + lane];
        unsigned m = __ballot_sync(0xffffffffu, v != 0.0f);
        if (lane == 0) g_adjbits[n * NW + w] = m;
    }
}

// ---------------- K4: fused P-build + tensor-core P@hv + normalize ----------------
__global__ __launch_bounds__(256, 2) void k4_main(float* __restrict__ out) {
    __shared__ __align__(16) __half2 Ps[2][RT][36];        // P tile, 144B row stride
    __shared__ __align__(16) __half  Hs[2][KC][HS_STRIDE]; // hv tile, 176B row stride
    __shared__ __align__(16) __half2 U2s[2][KC/2];
    __shared__ __align__(16) __half2 V2s[2][KC/2];
    __shared__ __align__(16) __half2 T2s[2][KC/2];
    __shared__ float dRow[RT];

    int head = blockIdx.y;
    int n0 = blockIdx.x * RT;
    int tid = threadIdx.x;
    int lane = tid & 31, wid = tid >> 5;
    int warp_m = wid >> 1;            // 0..3 -> 16-row tile
    int warp_n = (wid & 1) * 40;      // 0 or 40

    // per-thread P-build row constants
    int pr = tid >> 2;                // 0..63: row of P tile
    int q  = tid & 3;                 // which 16-col quarter of the 64 chunk
    __half2 e1 = g_e1[head * NROW + n0 + pr];
    __half2 e2 = g_e2[head * NROW + n0 + pr];
    __half2 nc = g_nc[head * NROW + n0 + pr];

    float acc[5][4];
    #pragma unroll
    for (int b = 0; b < 5; b++)
        #pragma unroll
        for (int c = 0; c < 4; c++) acc[b][c] = 0.0f;

    const float4* hv4 = (const float4*)&g_hv[head * NROW * NC];
    const __half* gu = g_u + head * NROW;
    const __half* gv = g_v + head * NROW;
    const __half* gt = g_th + head * NROW;

    // ---- pipelined load issue ----
    auto issue = [&](int kb, int s) {
        int m0 = kb * KC;
        #pragma unroll
        for (int i = 0; i < 3; i++) {
            int idx = tid + i * 256;
            if (idx < 640) {
                int r = idx / 10, cg = idx % 10;
                cp16(((char*)&Hs[s][r][0]) + cg * 16, (const char*)(hv4 + (m0 + r) * 10 + cg));
            }
        }
        if (tid < 24) {
            int a = tid >> 3, i = tid & 7;
            const __half* src = (a == 0 ? gu : (a == 1 ? gv : gt)) + m0 + i * 8;
            __half2* dst = (a == 0 ? &U2s[s][0] : (a == 1 ? &V2s[s][0] : &T2s[s][0])) + i * 4;
            cp16(dst, src);
        }
        cp_commit();
    };

    issue(0, 0);

    for (int kb = 0; kb < NITER; kb++) {
        int s = kb & 1;
        cp_wait_all();
        __syncthreads();                 // all warps past previous mma; tile s visible
        if (kb + 1 < NITER) issue(kb + 1, s ^ 1);

        // build P tile rows: P[n,m] = adj ? (t+c>0 ? e^c e^t : e^{ac} e^{at}) : 0
        {
            uint32_t bits = g_adjbits[(n0 + pr) * NW + kb * 2 + (q >> 1)];
            bits = (bits >> ((q & 1) * 16)) & 0xFFFFu;
            int pbase = q * 8;
            #pragma unroll
            for (int jj = 0; jj < 8; jj++) {
                __half2 pos = __hmul2(U2s[s][pbase + jj], e1);
                __half2 neg = __hmul2(V2s[s][pbase + jj], e2);
                uint32_t cm = __hgt2_mask(T2s[s][pbase + jj], nc);
                uint32_t pu = *(uint32_t*)&pos;
                uint32_t nu = *(uint32_t*)&neg;
                uint32_t r = (pu & cm) | (nu & ~cm);
                uint32_t b2 = bits >> (2 * jj);
                uint32_t am = ((b2 & 1u) ? 0x0000FFFFu : 0u) | ((b2 & 2u) ? 0xFFFF0000u : 0u);
                r &= am;
                Ps[s][pr][pbase + jj] = *(__half2*)&r;
            }
        }
        __syncthreads();

        // tensor-core accumulate: C[64x80] += P[64x64] @ Hs[64x80]
        const char* PsB = (const char*)&Ps[s][0][0];
        const char* HsB = (const char*)&Hs[s][0][0];
        #pragma unroll
        for (int kk = 0; kk < 4; kk++) {
            uint32_t a[4];
            {
                uint32_t addr = smem_u32(PsB + (warp_m * 16 + (lane & 15)) * 144
                                             + (kk * 16 + (lane >> 4) * 8) * 2);
                ldm_x4(a[0], a[1], a[2], a[3], addr);
            }
            uint32_t b[6][2];
            #pragma unroll
            for (int gg = 0; gg < 3; gg++) {
                uint32_t addr = smem_u32(HsB + (kk * 16 + (lane & 15)) * (HS_STRIDE * 2)
                                             + (warp_n + gg * 16 + (lane >> 4) * 8) * 2);
                ldm_x4_t(b[2 * gg][0], b[2 * gg][1], b[2 * gg + 1][0], b[2 * gg + 1][1], addr);
            }
            #pragma unroll
            for (int nt = 0; nt < 5; nt++)
                mma16816(&acc[nt][0], a, b[nt]);
        }
    }

    __syncthreads();
    // denominators: global col 64 -> odd warps (warp_n=40), nt=3, t4==0
    int g = lane >> 2, t4 = lane & 3;
    if ((wid & 1) == 1 && t4 == 0) {
        dRow[warp_m * 16 + g]     = acc[3][0];
        dRow[warp_m * 16 + 8 + g] = acc[3][2];
    }
    __syncthreads();

    // normalize + write out[n][head*64 + col]
    {
        int lr0 = warp_m * 16 + g;
        float inv0 = 1.0f / dRow[lr0];
        float inv1 = 1.0f / dRow[lr0 + 8];
        int row0 = n0 + lr0;
        #pragma unroll
        for (int nt = 0; nt < 5; nt++) {
            int col = warp_n + nt * 8 + 2 * t4;
            if (col < 64) {
                float* o0 = &out[row0 * (NH * OD) + head * OD + col];
                o0[0] = acc[nt][0] * inv0;
                o0[1] = acc[nt][1] * inv0;
                float* o1 = &out[(row0 + 8) * (NH * OD) + head * OD + col];
                o1[0] = acc[nt][2] * inv1;
                o1[1] = acc[nt][3] * inv1;
            }
        }
    }
}

// ---------------- launch ----------------
extern "C" void kernel_launch(void* const* d_in, const int* in_sizes, int n_in,
                              void* d_out, int out_size) {
    const float* x       = (const float*)d_in[0];
    const float* adj     = (const float*)d_in[1];
    const float* W       = (const float*)d_in[2];
    const float* a_self  = (const float*)d_in[3];
    const float* a_neigh = (const float*)d_in[4];
    float* out = (float*)d_out;

    k1_proj  <<<dim3(NROW / 64, NH), 256>>>(x, W);
    k2_scores<<<dim3(NROW / 8,  NH), 256>>>(a_self, a_neigh);
    k3_bits  <<<NROW, 128>>>(adj);
    k4_main  <<<dim3(NROW / RT, NH), 256>>>(out);
}

// round 4
// speedup vs baseline: 1.3159x; 1.0304x over previous
#include <cuda_runtime.h>
#include <cuda_fp16.h>
#include <cstdint>

#define NROW 4096
#define IND  128
#define OD   64
#define NH   4
#define NC   80          // padded hv cols: 64 h | col64 = 1.0 | 65..79 = 0
#define HS_STRIDE 88     // smem stride (halves) for hv tile
#define KC   64          // k-chunk (columns m per iteration)
#define RT   64          // row tile per block
#define NITER (NROW/KC)
#define ALPHAV 0.2f
#define NW   (NROW/32)   // adj bit words per row = 128

// ---------------- scratch (static device globals; no cudaMalloc) ----------------
__device__ float    g_h[NH*NROW*OD];        // 4 MB
__device__ __half   g_hv[NH*NROW*NC];       // 2.6 MB  (h fp16 + ones col + pad)
__device__ __half   g_u[NH*NROW];           // e^t
__device__ __half   g_v[NH*NROW];           // e^{0.2 t}
__device__ __half   g_th[NH*NROW];          // t (half)
__device__ __half2  g_e1[NH*NROW];          // (e^c, e^c)
__device__ __half2  g_e2[NH*NROW];          // (e^{0.2c}, e^{0.2c})
__device__ __half2  g_nc[NH*NROW];          // (-c, -c)
__device__ uint32_t g_adjbits[NROW*NW];     // 2 MB bit-packed adjacency

// ---------------- helpers ----------------
__device__ __forceinline__ uint32_t smem_u32(const void* p) {
    return (uint32_t)__cvta_generic_to_shared(p);
}
__device__ __forceinline__ void ldm_x4_t(uint32_t& r0, uint32_t& r1, uint32_t& r2, uint32_t& r3, uint32_t addr) {
    asm volatile("ldmatrix.sync.aligned.m8n8.x4.trans.shared.b16 {%0,%1,%2,%3}, [%4];"
                 : "=r"(r0), "=r"(r1), "=r"(r2), "=r"(r3) : "r"(addr));
}
__device__ __forceinline__ void mma16816(float* c, const uint32_t* a, const uint32_t* b) {
    asm volatile("mma.sync.aligned.m16n8k16.row.col.f32.f16.f16.f32 "
                 "{%0,%1,%2,%3}, {%4,%5,%6,%7}, {%8,%9}, {%0,%1,%2,%3};"
                 : "+f"(c[0]), "+f"(c[1]), "+f"(c[2]), "+f"(c[3])
                 : "r"(a[0]), "r"(a[1]), "r"(a[2]), "r"(a[3]), "r"(b[0]), "r"(b[1]));
}
__device__ __forceinline__ void cp16(void* smem_dst, const void* gmem_src) {
    asm volatile("cp.async.cg.shared.global [%0], [%1], 16;"
                 :: "r"(smem_u32(smem_dst)), "l"(gmem_src));
}
__device__ __forceinline__ void cp_commit() {
    asm volatile("cp.async.commit_group;");
}
__device__ __forceinline__ void cp_wait_all() {
    asm volatile("cp.async.wait_group 0;");
}

// P value for one (row, column-pair): select + adjacency mask
__device__ __forceinline__ uint32_t pval(__half2 u, __half2 v, __half2 t,
                                         __half2 e1, __half2 e2, __half2 nc,
                                         uint32_t w, int sh) {
    __half2 pos = __hmul2(u, e1);
    __half2 neg = __hmul2(v, e2);
    uint32_t cm = __hgt2_mask(t, nc);
    uint32_t r = ((*(uint32_t*)&pos) & cm) | ((*(uint32_t*)&neg) & ~cm);
    uint32_t b2 = (w >> sh) & 3u;
    uint32_t am = ((b2 & 1u) ? 0x0000FFFFu : 0u) | ((b2 & 2u) ? 0xFFFF0000u : 0u);
    return r & am;
}

// ---------------- K1: h = x @ W per head; also write hv fp16 (+ ones col) ----------------
__global__ __launch_bounds__(256) void k1_proj(const float* __restrict__ x,
                                               const float* __restrict__ W) {
    __shared__ float xs[64][65];
    __shared__ float ws[64][65];
    int head = blockIdx.y;
    int r0 = blockIdx.x * 64;
    int tid = threadIdx.x;
    int tx = tid & 15, ty = tid >> 4;
    float acc[4][4] = {};
    for (int k0 = 0; k0 < IND; k0 += 64) {
        for (int idx = tid; idx < 64 * 64; idx += 256) {
            int r = idx >> 6, c = idx & 63;
            xs[r][c] = x[(r0 + r) * IND + k0 + c];
            ws[r][c] = W[head * IND * OD + (k0 + r) * OD + c];
        }
        __syncthreads();
        for (int k = 0; k < 64; k++) {
            float wv[4];
            #pragma unroll
            for (int j = 0; j < 4; j++) wv[j] = ws[k][tx * 4 + j];
            #pragma unroll
            for (int i = 0; i < 4; i++) {
                float xv = xs[ty + 16 * i][k];
                #pragma unroll
                for (int j = 0; j < 4; j++) acc[i][j] += xv * wv[j];
            }
        }
        __syncthreads();
    }
    #pragma unroll
    for (int i = 0; i < 4; i++)
        #pragma unroll
        for (int j = 0; j < 4; j++) {
            int r = r0 + ty + 16 * i, c = tx * 4 + j;
            g_h[(head * NROW + r) * OD + c] = acc[i][j];
            g_hv[(head * NROW + r) * NC + c] = __float2half(acc[i][j]);
        }
    for (int idx = tid; idx < 64 * 16; idx += 256) {
        int r = idx >> 4, pc = idx & 15;
        g_hv[(head * NROW + r0 + r) * NC + 64 + pc] =
            (pc == 0) ? __float2half(1.0f) : __float2half(0.0f);
    }
}

// ---------------- K2: per (head,n): c = h.a_self, t = h.a_neigh; pack exps ----------------
__global__ __launch_bounds__(256) void k2_scores(const float* __restrict__ a_self,
                                                 const float* __restrict__ a_neigh) {
    int head = blockIdx.y;
    int n = blockIdx.x * 8 + (threadIdx.x >> 5);
    int lane = threadIdx.x & 31;
    const float2* hp = (const float2*)&g_h[(head * NROW + n) * OD];
    float2 hv = hp[lane];
    float2 asv = ((const float2*)(a_self + head * OD))[lane];
    float2 anv = ((const float2*)(a_neigh + head * OD))[lane];
    float ps = hv.x * asv.x + hv.y * asv.y;
    float pn = hv.x * anv.x + hv.y * anv.y;
    #pragma unroll
    for (int o = 16; o > 0; o >>= 1) {
        ps += __shfl_xor_sync(0xffffffffu, ps, o);
        pn += __shfl_xor_sync(0xffffffffu, pn, o);
    }
    if (lane == 0) {
        float c = ps, t = pn;
        int i = head * NROW + n;
        g_u[i]  = __float2half(expf(t));
        g_v[i]  = __float2half(expf(ALPHAV * t));
        g_th[i] = __float2half(t);
        g_e1[i] = __float2half2_rn(expf(c));
        g_e2[i] = __float2half2_rn(expf(ALPHAV * c));
        g_nc[i] = __float2half2_rn(-c);
    }
}

// ---------------- K3: bit-pack adjacency (float4 + nibble smem pack) ----------------
__global__ __launch_bounds__(256) void k3_bits(const float* __restrict__ adj) {
    __shared__ __align__(8) uint8_t nib[1024];
    int n = blockIdx.x;
    int tid = threadIdx.x;
    const float4* row = (const float4*)(adj + (size_t)n * NROW);
    float4 v[4];
    #pragma unroll
    for (int p = 0; p < 4; p++) v[p] = row[p * 256 + tid];
    #pragma unroll
    for (int p = 0; p < 4; p++) {
        uint32_t b = (v[p].x != 0.0f) | ((v[p].y != 0.0f) << 1) |
                     ((v[p].z != 0.0f) << 2) | ((v[p].w != 0.0f) << 3);
        nib[p * 256 + tid] = (uint8_t)b;   // nib[i] covers cols 4i..4i+3
    }
    __syncthreads();
    if (tid < 128) {
        uint2 b8 = *(const uint2*)&nib[8 * tid];
        uint32_t tlo = b8.x | (b8.x >> 4);
        uint32_t thi = b8.y | (b8.y >> 4);
        uint32_t w32 = __byte_perm(tlo, 0, 0x4420) | (__byte_perm(thi, 0, 0x4420) << 16);
        g_adjbits[n * NW + tid] = w32;
    }
}

// ---------------- K4: fused in-register P-build + tensor-core P@hv + normalize ----------------
__global__ __launch_bounds__(256, 3) void k4_main(float* __restrict__ out) {
    __shared__ __align__(16) __half  Hs[2][KC][HS_STRIDE]; // hv tile, 176B row stride
    __shared__ __align__(16) __half2 U2s[2][KC/2];
    __shared__ __align__(16) __half2 V2s[2][KC/2];
    __shared__ __align__(16) __half2 T2s[2][KC/2];
    __shared__ float dRow[RT];

    int head = blockIdx.y;
    int n0 = blockIdx.x * RT;
    int tid = threadIdx.x;
    int lane = tid & 31, wid = tid >> 5;
    int warp_m = wid >> 1;            // 0..3 -> 16-row tile
    int warp_n = (wid & 1) * 40;      // 0 or 40
    int g = lane >> 2, tc = lane & 3;

    // the two P rows this thread owns in the mma A fragment
    int ra = n0 + warp_m * 16 + g;    // rows g and g+8 of the 16-row tile
    int rb = ra + 8;
    int ia = head * NROW + ra, ib = head * NROW + rb;
    __half2 e1a = g_e1[ia], e2a = g_e2[ia], nca = g_nc[ia];
    __half2 e1b = g_e1[ib], e2b = g_e2[ib], ncb = g_nc[ib];
    const uint2* adjA = (const uint2*)&g_adjbits[ra * NW];  // [kb] -> 64 cols
    const uint2* adjB = (const uint2*)&g_adjbits[rb * NW];

    float acc[5][4];
    #pragma unroll
    for (int b = 0; b < 5; b++)
        #pragma unroll
        for (int c = 0; c < 4; c++) acc[b][c] = 0.0f;

    const float4* hv4 = (const float4*)&g_hv[head * NROW * NC];
    const __half* gu = g_u + head * NROW;
    const __half* gv = g_v + head * NROW;
    const __half* gt = g_th + head * NROW;

    auto issue = [&](int kb, int s) {
        int m0 = kb * KC;
        #pragma unroll
        for (int i = 0; i < 3; i++) {
            int idx = tid + i * 256;
            if (idx < 640) {
                int r = idx / 10, cg = idx % 10;
                cp16(((char*)&Hs[s][r][0]) + cg * 16, (const char*)(hv4 + (m0 + r) * 10 + cg));
            }
        }
        if (tid < 24) {
            int a = tid >> 3, i = tid & 7;
            const __half* src = (a == 0 ? gu : (a == 1 ? gv : gt)) + m0 + i * 8;
            __half2* dst = (a == 0 ? &U2s[s][0] : (a == 1 ? &V2s[s][0] : &T2s[s][0])) + i * 4;
            cp16(dst, src);
        }
        cp_commit();
    };

    issue(0, 0);
    uint2 awa = __ldg(&adjA[0]);
    uint2 awb = __ldg(&adjB[0]);

    for (int kb = 0; kb < NITER; kb++) {
        int s = kb & 1;
        cp_wait_all();
        __syncthreads();                 // tile s visible; all warps done with s^1
        if (kb + 1 < NITER) issue(kb + 1, s ^ 1);
        uint2 nwa = make_uint2(0u, 0u), nwb = make_uint2(0u, 0u);
        if (kb + 1 < NITER) {
            nwa = __ldg(&adjA[kb + 1]);
            nwb = __ldg(&adjB[kb + 1]);
        }

        const char* HsB = (const char*)&Hs[s][0][0];
        #pragma unroll
        for (int kk = 0; kk < 4; kk++) {
            int p0 = kk * 8 + tc;       // column-pair indices for this k-step
            int p1 = p0 + 4;
            uint32_t wa = (kk < 2) ? awa.x : awa.y;
            uint32_t wb = (kk < 2) ? awb.x : awb.y;
            int sh0 = (2 * p0) & 31;
            int sh1 = (2 * p1) & 31;

            __half2 u0 = U2s[s][p0], v0 = V2s[s][p0], t0 = T2s[s][p0];
            __half2 u1 = U2s[s][p1], v1 = V2s[s][p1], t1 = T2s[s][p1];

            uint32_t a[4];
            a[0] = pval(u0, v0, t0, e1a, e2a, nca, wa, sh0);
            a[1] = pval(u0, v0, t0, e1b, e2b, ncb, wb, sh0);
            a[2] = pval(u1, v1, t1, e1a, e2a, nca, wa, sh1);
            a[3] = pval(u1, v1, t1, e1b, e2b, ncb, wb, sh1);

            uint32_t b[6][2];
            #pragma unroll
            for (int gg = 0; gg < 3; gg++) {
                uint32_t addr = smem_u32(HsB + (kk * 16 + (lane & 15)) * (HS_STRIDE * 2)
                                             + (warp_n + gg * 16 + (lane >> 4) * 8) * 2);
                ldm_x4_t(b[2 * gg][0], b[2 * gg][1], b[2 * gg + 1][0], b[2 * gg + 1][1], addr);
            }
            #pragma unroll
            for (int nt = 0; nt < 5; nt++)
                mma16816(&acc[nt][0], a, b[nt]);
        }
        awa = nwa;
        awb = nwb;
    }

    __syncthreads();
    // denominators: global col 64 -> odd warps (warp_n=40), nt=3, tc==0
    if ((wid & 1) == 1 && tc == 0) {
        dRow[warp_m * 16 + g]     = acc[3][0];
        dRow[warp_m * 16 + 8 + g] = acc[3][2];
    }
    __syncthreads();

    // normalize + write out[n][head*64 + col]
    {
        int lr0 = warp_m * 16 + g;
        float inv0 = 1.0f / dRow[lr0];
        float inv1 = 1.0f / dRow[lr0 + 8];
        int row0 = n0 + lr0;
        #pragma unroll
        for (int nt = 0; nt < 5; nt++) {
            int col = warp_n + nt * 8 + 2 * tc;
            if (col < 64) {
                float* o0 = &out[row0 * (NH * OD) + head * OD + col];
                o0[0] = acc[nt][0] * inv0;
                o0[1] = acc[nt][1] * inv0;
                float* o1 = &out[(row0 + 8) * (NH * OD) + head * OD + col];
                o1[0] = acc[nt][2] * inv1;
                o1[1] = acc[nt][3] * inv1;
            }
        }
    }
}

// ---------------- launch ----------------
extern "C" void kernel_launch(void* const* d_in, const int* in_sizes, int n_in,
                              void* d_out, int out_size) {
    const float* x       = (const float*)d_in[0];
    const float* adj     = (const float*)d_in[1];
    const float* W       = (const float*)d_in[2];
    const float* a_self  = (const float*)d_in[3];
    const float* a_neigh = (const float*)d_in[4];
    float* out = (float*)d_out;

    k1_proj  <<<dim3(NROW / 64, NH), 256>>>(x, W);
    k2_scores<<<dim3(NROW / 8,  NH), 256>>>(a_self, a_neigh);
    k3_bits  <<<NROW, 256>>>(adj);
    k4_main  <<<dim3(NROW / RT, NH), 256>>>(out);
}

// round 5
// speedup vs baseline: 1.4271x; 1.0845x over previous
#include <cuda_runtime.h>
#include <cuda_fp16.h>
#include <cstdint>

#define NROW 4096
#define IND  128
#define OD   64
#define NH   4
#define NC   80          // padded hv cols: 64 h | col64 = 1.0 | 65..79 = 0
#define HS_STRIDE 88     // smem stride (halves) for hv tile
#define KC   64          // k-chunk (columns m per iteration)
#define RT   64          // row tile per block
#define KSPLIT 2
#define ITER_PER (NROW/KC/KSPLIT)   // 32
#define NW   (NROW/32)   // adj bit words per row = 128

// ---------------- scratch (static device globals; no cudaMalloc) ----------------
__device__ __half   g_hv[NH*NROW*NC];       // 2.6 MB  (h fp16 + ones col + pad)
__device__ __half   g_u[NH*NROW];           // e^t
__device__ __half   g_v[NH*NROW];           // e^{0.2 t}
__device__ __half   g_th[NH*NROW];          // t (half)
__device__ __half2  g_E2[NH*NROW];          // (e^{0.8c}, e^{0.8c})
__device__ __half2  g_nc[NH*NROW];          // (-c, -c)
__device__ uint32_t g_adjbits[NROW*NW];     // 2 MB bit-packed adjacency
__device__ float    g_part[KSPLIT*NH*NROW*80]; // 10.5 MB split-K partials

// ---------------- helpers ----------------
__device__ __forceinline__ uint32_t smem_u32(const void* p) {
    return (uint32_t)__cvta_generic_to_shared(p);
}
__device__ __forceinline__ void ldm_x4_t(uint32_t& r0, uint32_t& r1, uint32_t& r2, uint32_t& r3, uint32_t addr) {
    asm volatile("ldmatrix.sync.aligned.m8n8.x4.trans.shared.b16 {%0,%1,%2,%3}, [%4];"
                 : "=r"(r0), "=r"(r1), "=r"(r2), "=r"(r3) : "r"(addr));
}
__device__ __forceinline__ void mma16816(float* c, const uint32_t* a, const uint32_t* b) {
    asm volatile("mma.sync.aligned.m16n8k16.row.col.f32.f16.f16.f32 "
                 "{%0,%1,%2,%3}, {%4,%5,%6,%7}, {%8,%9}, {%0,%1,%2,%3};"
                 : "+f"(c[0]), "+f"(c[1]), "+f"(c[2]), "+f"(c[3])
                 : "r"(a[0]), "r"(a[1]), "r"(a[2]), "r"(a[3]), "r"(b[0]), "r"(b[1]));
}
__device__ __forceinline__ void cp16(void* smem_dst, const void* gmem_src) {
    asm volatile("cp.async.cg.shared.global [%0], [%1], 16;"
                 :: "r"(smem_u32(smem_dst)), "l"(gmem_src));
}
__device__ __forceinline__ void cp_commit() {
    asm volatile("cp.async.commit_group;");
}
__device__ __forceinline__ void cp_wait_all() {
    asm volatile("cp.async.wait_group 0;");
}

// P value for one (row, column-pair), with the e^{0.2c} row factor divided out:
//   P = adj ? (t > -c ? e^{0.8c} * e^t : e^{0.2t}) : 0
__device__ __forceinline__ uint32_t pval(__half2 u, __half2 v, __half2 t,
                                         __half2 E, __half2 nc,
                                         uint32_t w, int sh) {
    __half2 pos = __hmul2(u, E);
    uint32_t cm = __hgt2_mask(t, nc);
    uint32_t r = ((*(uint32_t*)&pos) & cm) | ((*(uint32_t*)&v) & ~cm);
    uint32_t b2 = (w >> sh) & 3u;
    uint32_t am = ((b2 & 1u) ? 0x0000FFFFu : 0u) | ((b2 & 2u) ? 0xFFFF0000u : 0u);
    return r & am;
}

// ---------------- KA: fused  proj(h=xW)+scores  and  adjacency bit-pack ----------------
// blocks [0, 256):        projection tiles (64 rows x head), + per-row score exps
// blocks [256, 256+4096): one adjacency row each -> bit pack
__global__ __launch_bounds__(256) void kA(const float* __restrict__ x,
                                          const float* __restrict__ adj,
                                          const float* __restrict__ W,
                                          const float* __restrict__ a_self,
                                          const float* __restrict__ a_neigh) {
    __shared__ float xs[64][65];
    __shared__ float ws[64][65];
    __shared__ __align__(8) uint8_t nib[1024];
    int bid = blockIdx.x;
    int tid = threadIdx.x;

    if (bid >= 256) {
        // ---- adjacency bit-pack: one row ----
        int n = bid - 256;
        const float4* row = (const float4*)(adj + (size_t)n * NROW);
        float4 v[4];
        #pragma unroll
        for (int p = 0; p < 4; p++) v[p] = row[p * 256 + tid];
        #pragma unroll
        for (int p = 0; p < 4; p++) {
            uint32_t b = (v[p].x != 0.0f) | ((v[p].y != 0.0f) << 1) |
                         ((v[p].z != 0.0f) << 2) | ((v[p].w != 0.0f) << 3);
            nib[p * 256 + tid] = (uint8_t)b;
        }
        __syncthreads();
        if (tid < 128) {
            uint2 b8 = *(const uint2*)&nib[8 * tid];
            uint32_t tlo = b8.x | (b8.x >> 4);
            uint32_t thi = b8.y | (b8.y >> 4);
            uint32_t w32 = __byte_perm(tlo, 0, 0x4420) | (__byte_perm(thi, 0, 0x4420) << 16);
            g_adjbits[n * NW + tid] = w32;
        }
        return;
    }

    // ---- projection tile ----
    int head = bid >> 6;
    int r0 = (bid & 63) * 64;
    int tx = tid & 15, ty = tid >> 4;
    float acc[4][4] = {};
    for (int k0 = 0; k0 < IND; k0 += 64) {
        for (int idx = tid; idx < 64 * 64; idx += 256) {
            int r = idx >> 6, c = idx & 63;
            xs[r][c] = x[(r0 + r) * IND + k0 + c];
            ws[r][c] = W[head * IND * OD + (k0 + r) * OD + c];
        }
        __syncthreads();
        for (int k = 0; k < 64; k++) {
            float wv[4];
            #pragma unroll
            for (int j = 0; j < 4; j++) wv[j] = ws[k][tx * 4 + j];
            #pragma unroll
            for (int i = 0; i < 4; i++) {
                float xv = xs[ty + 16 * i][k];
                #pragma unroll
                for (int j = 0; j < 4; j++) acc[i][j] += xv * wv[j];
            }
        }
        __syncthreads();
    }
    // hv (fp16) + pad cols
    #pragma unroll
    for (int i = 0; i < 4; i++)
        #pragma unroll
        for (int j = 0; j < 4; j++) {
            int r = r0 + ty + 16 * i, c = tx * 4 + j;
            g_hv[(head * NROW + r) * NC + c] = __float2half(acc[i][j]);
        }
    for (int idx = tid; idx < 64 * 16; idx += 256) {
        int r = idx >> 4, pc = idx & 15;
        g_hv[(head * NROW + r0 + r) * NC + 64 + pc] =
            (pc == 0) ? __float2half(1.0f) : __float2half(0.0f);
    }
    // score dot partials (reuse xs as scratch: 2048 floats)
    float as[4], an[4];
    #pragma unroll
    for (int j = 0; j < 4; j++) {
        as[j] = __ldg(&a_self[head * OD + tx * 4 + j]);
        an[j] = __ldg(&a_neigh[head * OD + tx * 4 + j]);
    }
    float* sp = &xs[0][0];
    #pragma unroll
    for (int i = 0; i < 4; i++) {
        float ps = 0.f, pn = 0.f;
        #pragma unroll
        for (int j = 0; j < 4; j++) { ps += acc[i][j] * as[j]; pn += acc[i][j] * an[j]; }
        int row = ty + 16 * i;
        sp[row * 16 + tx] = ps;
        sp[1024 + row * 16 + tx] = pn;
    }
    __syncthreads();
    if (tid < 64) {
        float c = 0.f, t = 0.f;
        #pragma unroll
        for (int xq = 0; xq < 16; xq++) {
            c += sp[tid * 16 + xq];
            t += sp[1024 + tid * 16 + xq];
        }
        int i = head * NROW + r0 + tid;
        g_u[i]  = __float2half(expf(t));
        g_v[i]  = __float2half(expf(0.2f * t));
        g_th[i] = __float2half(t);
        g_E2[i] = __float2half2_rn(expf(0.8f * c));
        g_nc[i] = __float2half2_rn(-c);
    }
}

// ---------------- K4: split-K fused P-build + tensor-core P@hv -> partials ----------------
__global__ __launch_bounds__(256, 4) void k4_main() {
    __shared__ __align__(16) __half  Hs[2][KC][HS_STRIDE];
    __shared__ __align__(16) __half2 U2s[2][KC/2];
    __shared__ __align__(16) __half2 V2s[2][KC/2];
    __shared__ __align__(16) __half2 T2s[2][KC/2];

    int head = blockIdx.y;
    int n0 = blockIdx.x * RT;
    int z = blockIdx.z;                  // k-split index
    int kb0 = z * ITER_PER;
    int tid = threadIdx.x;
    int lane = tid & 31, wid = tid >> 5;
    int warp_m = wid >> 1;               // 0..3 -> 16-row tile
    int warp_n = (wid & 1) * 40;         // 0 or 40
    int g = lane >> 2, tc = lane & 3;

    int ra = n0 + warp_m * 16 + g;
    int rb = ra + 8;
    int ia = head * NROW + ra, ib = head * NROW + rb;
    __half2 Ea = g_E2[ia], nca = g_nc[ia];
    __half2 Eb = g_E2[ib], ncb = g_nc[ib];
    const uint2* adjA = (const uint2*)&g_adjbits[ra * NW];  // [kb] -> 64 cols
    const uint2* adjB = (const uint2*)&g_adjbits[rb * NW];

    float acc[5][4];
    #pragma unroll
    for (int b = 0; b < 5; b++)
        #pragma unroll
        for (int c = 0; c < 4; c++) acc[b][c] = 0.0f;

    const float4* hv4 = (const float4*)&g_hv[head * NROW * NC];
    const __half* gu = g_u + head * NROW;
    const __half* gv = g_v + head * NROW;
    const __half* gt = g_th + head * NROW;

    auto issue = [&](int kbg, int s) {
        int m0 = kbg * KC;
        #pragma unroll
        for (int i = 0; i < 3; i++) {
            int idx = tid + i * 256;
            if (idx < 640) {
                int r = idx / 10, cg = idx % 10;
                cp16(((char*)&Hs[s][r][0]) + cg * 16, (const char*)(hv4 + (m0 + r) * 10 + cg));
            }
        }
        if (tid < 24) {
            int a = tid >> 3, i = tid & 7;
            const __half* src = (a == 0 ? gu : (a == 1 ? gv : gt)) + m0 + i * 8;
            __half2* dst = (a == 0 ? &U2s[s][0] : (a == 1 ? &V2s[s][0] : &T2s[s][0])) + i * 4;
            cp16(dst, src);
        }
        cp_commit();
    };

    issue(kb0, 0);
    uint2 awa = __ldg(&adjA[kb0]);
    uint2 awb = __ldg(&adjB[kb0]);

    for (int k2 = 0; k2 < ITER_PER; k2++) {
        int s = k2 & 1;
        cp_wait_all();
        __syncthreads();
        if (k2 + 1 < ITER_PER) issue(kb0 + k2 + 1, s ^ 1);
        uint2 nwa = make_uint2(0u, 0u), nwb = make_uint2(0u, 0u);
        if (k2 + 1 < ITER_PER) {
            nwa = __ldg(&adjA[kb0 + k2 + 1]);
            nwb = __ldg(&adjB[kb0 + k2 + 1]);
        }

        const char* HsB = (const char*)&Hs[s][0][0];
        #pragma unroll
        for (int kk = 0; kk < 4; kk++) {
            int p0 = kk * 8 + tc;
            int p1 = p0 + 4;
            uint32_t wa = (kk < 2) ? awa.x : awa.y;
            uint32_t wb = (kk < 2) ? awb.x : awb.y;
            int sh0 = (2 * p0) & 31;
            int sh1 = (2 * p1) & 31;

            __half2 u0 = U2s[s][p0], v0 = V2s[s][p0], t0 = T2s[s][p0];
            __half2 u1 = U2s[s][p1], v1 = V2s[s][p1], t1 = T2s[s][p1];

            uint32_t a[4];
            a[0] = pval(u0, v0, t0, Ea, nca, wa, sh0);
            a[1] = pval(u0, v0, t0, Eb, ncb, wb, sh0);
            a[2] = pval(u1, v1, t1, Ea, nca, wa, sh1);
            a[3] = pval(u1, v1, t1, Eb, ncb, wb, sh1);

            const char* rowB = HsB + (kk * 16 + (lane & 15)) * (HS_STRIDE * 2)
                                   + ((lane >> 4) * 8) * 2;
            // nt 0..3 via two x4 loads, mma immediately to limit live regs
            #pragma unroll
            for (int gg = 0; gg < 2; gg++) {
                uint32_t b0[2], b1[2];
                ldm_x4_t(b0[0], b0[1], b1[0], b1[1],
                         smem_u32(rowB + (warp_n + gg * 16) * 2));
                mma16816(&acc[2 * gg][0], a, b0);
                mma16816(&acc[2 * gg + 1][0], a, b1);
            }
            // nt 4: x4 load at +32 cols; second half (cols +40..47) unused
            {
                uint32_t b0[2], b1[2];
                ldm_x4_t(b0[0], b0[1], b1[0], b1[1],
                         smem_u32(rowB + (warp_n + 32) * 2));
                mma16816(&acc[4][0], a, b0);
                (void)b1;
            }
        }
        awa = nwa;
        awb = nwb;
    }

    // store unnormalized partials (all 80 cols incl. denominator col 64)
    float* pb = g_part + ((size_t)(z * NH + head) * NROW) * 80;
    int row0 = n0 + warp_m * 16 + g;
    #pragma unroll
    for (int nt = 0; nt < 5; nt++) {
        int col = warp_n + nt * 8 + 2 * tc;
        *(float2*)&pb[(size_t)row0 * 80 + col] = make_float2(acc[nt][0], acc[nt][1]);
        *(float2*)&pb[(size_t)(row0 + 8) * 80 + col] = make_float2(acc[nt][2], acc[nt][3]);
    }
}

// ---------------- K5: combine split-K partials + normalize + write out ----------------
__global__ __launch_bounds__(256) void k5_combine(float* __restrict__ out) {
    int head = blockIdx.y;
    int r = blockIdx.x * 64 + (threadIdx.x >> 2);
    int q = threadIdx.x & 3;
    const float* p0 = g_part + ((size_t)(0 * NH + head) * NROW + r) * 80;
    const float* p1 = g_part + ((size_t)(1 * NH + head) * NROW + r) * 80;
    float inv = 1.0f / (p0[64] + p1[64]);
    #pragma unroll
    for (int j = 0; j < 4; j++) {
        float4 a = *(const float4*)&p0[q * 16 + j * 4];
        float4 b = *(const float4*)&p1[q * 16 + j * 4];
        float4 o;
        o.x = (a.x + b.x) * inv;
        o.y = (a.y + b.y) * inv;
        o.z = (a.z + b.z) * inv;
        o.w = (a.w + b.w) * inv;
        *(float4*)&out[(size_t)r * (NH * OD) + head * OD + q * 16 + j * 4] = o;
    }
}

// ---------------- launch ----------------
extern "C" void kernel_launch(void* const* d_in, const int* in_sizes, int n_in,
                              void* d_out, int out_size) {
    const float* x       = (const float*)d_in[0];
    const float* adj     = (const float*)d_in[1];
    const float* W       = (const float*)d_in[2];
    const float* a_self  = (const float*)d_in[3];
    const float* a_neigh = (const float*)d_in[4];
    float* out = (float*)d_out;

    kA        <<<256 + NROW, 256>>>(x, adj, W, a_self, a_neigh);
    k4_main   <<<dim3(NROW / RT, NH, KSPLIT), 256>>>();
    k5_combine<<<dim3(NROW / 64, NH), 256>>>(out);
}

// round 6
// speedup vs baseline: 1.5732x; 1.1024x over previous
#include <cuda_runtime.h>
#include <cuda_fp16.h>
#include <cstdint>

#define NROW 4096
#define IND  128
#define OD   64
#define NH   4
#define NC   80          // padded hv cols: 64 h | col64 = 1.0 | 65..79 = 0
#define HS_STRIDE 88     // smem stride (halves) for hv tile
#define KC   64          // k-chunk (columns m per iteration)
#define RT   64          // row tile per block
#define KSPLIT 2
#define ITER_PER (NROW/KC/KSPLIT)   // 32
#define NW   (NROW/32)   // adj bit words per row = 128

// ---------------- scratch (static device globals; no cudaMalloc) ----------------
__device__ __half   g_hv[NH*NROW*NC];       // 2.6 MB  (h fp16 + ones col + pad)
__device__ __half   g_u[NH*NROW];           // e^t
__device__ __half   g_v[NH*NROW];           // e^{0.2 t}
__device__ __half   g_th[NH*NROW];          // t (half)
__device__ __half2  g_E2[NH*NROW];          // (e^{0.8c}, e^{0.8c})
__device__ __half2  g_nc[NH*NROW];          // (-c, -c)
__device__ uint32_t g_adjbits[NROW*NW];     // 2 MB bit-packed adjacency
__device__ float    g_part[KSPLIT*NH*NROW*80]; // 10.5 MB split-K partials

// ---------------- helpers ----------------
__device__ __forceinline__ uint32_t smem_u32(const void* p) {
    return (uint32_t)__cvta_generic_to_shared(p);
}
__device__ __forceinline__ void ldm_x4_t(uint32_t& r0, uint32_t& r1, uint32_t& r2, uint32_t& r3, uint32_t addr) {
    asm volatile("ldmatrix.sync.aligned.m8n8.x4.trans.shared.b16 {%0,%1,%2,%3}, [%4];"
                 : "=r"(r0), "=r"(r1), "=r"(r2), "=r"(r3) : "r"(addr));
}
__device__ __forceinline__ void mma16816(float* c, const uint32_t* a, const uint32_t* b) {
    asm volatile("mma.sync.aligned.m16n8k16.row.col.f32.f16.f16.f32 "
                 "{%0,%1,%2,%3}, {%4,%5,%6,%7}, {%8,%9}, {%0,%1,%2,%3};"
                 : "+f"(c[0]), "+f"(c[1]), "+f"(c[2]), "+f"(c[3])
                 : "r"(a[0]), "r"(a[1]), "r"(a[2]), "r"(a[3]), "r"(b[0]), "r"(b[1]));
}
__device__ __forceinline__ void cp16(void* smem_dst, const void* gmem_src) {
    asm volatile("cp.async.cg.shared.global [%0], [%1], 16;"
                 :: "r"(smem_u32(smem_dst)), "l"(gmem_src));
}
__device__ __forceinline__ void cp_commit() {
    asm volatile("cp.async.commit_group;");
}
__device__ __forceinline__ void cp_wait_all() {
    asm volatile("cp.async.wait_group 0;");
}

// P value for one (row, column-pair), with the e^{0.2c} row factor divided out:
//   P = adj ? (t > -c ? e^{0.8c} * e^t : e^{0.2t}) : 0
__device__ __forceinline__ uint32_t pval(__half2 u, __half2 v, __half2 t,
                                         __half2 E, __half2 nc,
                                         uint32_t w, int sh) {
    __half2 pos = __hmul2(u, E);
    uint32_t cm = __hgt2_mask(t, nc);
    uint32_t r = ((*(uint32_t*)&pos) & cm) | ((*(uint32_t*)&v) & ~cm);
    uint32_t b2 = (w >> sh) & 3u;
    uint32_t am = ((b2 & 1u) ? 0x0000FFFFu : 0u) | ((b2 & 2u) ? 0xFFFF0000u : 0u);
    return r & am;
}

// ---------------- KA: fused adjacency bit-pack (first) + proj/scores (last) ----------------
// blocks [0, 4096):          one adjacency row each -> bit pack (DRAM stream starts at t=0)
// blocks [4096, 4096+256):   projection tiles (64 rows x head), + per-row score exps
__global__ __launch_bounds__(256) void kA(const float* __restrict__ x,
                                          const float* __restrict__ adj,
                                          const float* __restrict__ W,
                                          const float* __restrict__ a_self,
                                          const float* __restrict__ a_neigh) {
    __shared__ float xs[64][65];
    __shared__ float ws[64][68];
    __shared__ __align__(8) uint8_t nib[1024];
    int bid = blockIdx.x;
    int tid = threadIdx.x;

    if (bid < NROW) {
        // ---- adjacency bit-pack: one row ----
        int n = bid;
        const float4* row = (const float4*)(adj + (size_t)n * NROW);
        float4 v[4];
        #pragma unroll
        for (int p = 0; p < 4; p++) v[p] = row[p * 256 + tid];
        #pragma unroll
        for (int p = 0; p < 4; p++) {
            uint32_t b = (v[p].x != 0.0f) | ((v[p].y != 0.0f) << 1) |
                         ((v[p].z != 0.0f) << 2) | ((v[p].w != 0.0f) << 3);
            nib[p * 256 + tid] = (uint8_t)b;
        }
        __syncthreads();
        if (tid < 128) {
            uint2 b8 = *(const uint2*)&nib[8 * tid];
            uint32_t tlo = b8.x | (b8.x >> 4);
            uint32_t thi = b8.y | (b8.y >> 4);
            uint32_t w32 = __byte_perm(tlo, 0, 0x4420) | (__byte_perm(thi, 0, 0x4420) << 16);
            g_adjbits[n * NW + tid] = w32;
        }
        return;
    }

    // ---- projection tile ----
    int pbid = bid - NROW;
    int head = pbid >> 6;
    int r0 = (pbid & 63) * 64;
    int tx = tid & 15, ty = tid >> 4;
    float acc[4][4] = {};
    for (int k0 = 0; k0 < IND; k0 += 64) {
        for (int idx = tid; idx < 64 * 64; idx += 256) {
            int r = idx >> 6, c = idx & 63;
            xs[r][c] = x[(r0 + r) * IND + k0 + c];
            ws[r][c] = W[head * IND * OD + (k0 + r) * OD + c];
        }
        __syncthreads();
        for (int k = 0; k < 64; k++) {
            float4 wv = *(const float4*)&ws[k][tx * 4];
            #pragma unroll
            for (int i = 0; i < 4; i++) {
                float xv = xs[ty + 16 * i][k];
                acc[i][0] += xv * wv.x;
                acc[i][1] += xv * wv.y;
                acc[i][2] += xv * wv.z;
                acc[i][3] += xv * wv.w;
            }
        }
        __syncthreads();
    }
    // hv (fp16) + pad cols
    #pragma unroll
    for (int i = 0; i < 4; i++)
        #pragma unroll
        for (int j = 0; j < 4; j++) {
            int r = r0 + ty + 16 * i, c = tx * 4 + j;
            g_hv[(head * NROW + r) * NC + c] = __float2half(acc[i][j]);
        }
    for (int idx = tid; idx < 64 * 16; idx += 256) {
        int r = idx >> 4, pc = idx & 15;
        g_hv[(head * NROW + r0 + r) * NC + 64 + pc] =
            (pc == 0) ? __float2half(1.0f) : __float2half(0.0f);
    }
    // score dot partials (reuse xs as scratch: 2048 floats)
    float as[4], an[4];
    #pragma unroll
    for (int j = 0; j < 4; j++) {
        as[j] = __ldg(&a_self[head * OD + tx * 4 + j]);
        an[j] = __ldg(&a_neigh[head * OD + tx * 4 + j]);
    }
    float* sp = &xs[0][0];
    #pragma unroll
    for (int i = 0; i < 4; i++) {
        float ps = 0.f, pn = 0.f;
        #pragma unroll
        for (int j = 0; j < 4; j++) { ps += acc[i][j] * as[j]; pn += acc[i][j] * an[j]; }
        int row = ty + 16 * i;
        sp[row * 16 + tx] = ps;
        sp[1024 + row * 16 + tx] = pn;
    }
    __syncthreads();
    if (tid < 64) {
        float c = 0.f, t = 0.f;
        #pragma unroll
        for (int xq = 0; xq < 16; xq++) {
            c += sp[tid * 16 + xq];
            t += sp[1024 + tid * 16 + xq];
        }
        int i = head * NROW + r0 + tid;
        g_u[i]  = __float2half(expf(t));
        g_v[i]  = __float2half(expf(0.2f * t));
        g_th[i] = __float2half(t);
        g_E2[i] = __float2half2_rn(expf(0.8f * c));
        g_nc[i] = __float2half2_rn(-c);
    }
}

// ---------------- K4: split-K, 1 warp per 16-row m-tile, full N=80 per warp ----------------
__global__ __launch_bounds__(128, 5) void k4_main() {
    __shared__ __align__(16) __half  Hs[2][KC][HS_STRIDE];
    __shared__ __align__(16) __half2 U2s[2][KC/2];
    __shared__ __align__(16) __half2 V2s[2][KC/2];
    __shared__ __align__(16) __half2 T2s[2][KC/2];

    int head = blockIdx.y;
    int n0 = blockIdx.x * RT;
    int z = blockIdx.z;                  // k-split index
    int kb0 = z * ITER_PER;
    int tid = threadIdx.x;
    int lane = tid & 31, wid = tid >> 5; // wid = m-tile 0..3
    int g = lane >> 2, tc = lane & 3;

    int ra = n0 + wid * 16 + g;
    int rb = ra + 8;
    int ia = head * NROW + ra, ib = head * NROW + rb;
    __half2 Ea = g_E2[ia], nca = g_nc[ia];
    __half2 Eb = g_E2[ib], ncb = g_nc[ib];
    const uint2* adjA = (const uint2*)&g_adjbits[ra * NW];  // [kb] -> 64 cols
    const uint2* adjB = (const uint2*)&g_adjbits[rb * NW];

    float acc[10][4];
    #pragma unroll
    for (int b = 0; b < 10; b++)
        #pragma unroll
        for (int c = 0; c < 4; c++) acc[b][c] = 0.0f;

    const float4* hv4 = (const float4*)&g_hv[head * NROW * NC];
    const __half* gu = g_u + head * NROW;
    const __half* gv = g_v + head * NROW;
    const __half* gt = g_th + head * NROW;

    auto issue = [&](int kbg, int s) {
        int m0 = kbg * KC;
        #pragma unroll
        for (int i = 0; i < 5; i++) {
            int idx = tid + i * 128;
            int r = idx / 10, cg = idx % 10;
            cp16(((char*)&Hs[s][r][0]) + cg * 16, (const char*)(hv4 + (m0 + r) * 10 + cg));
        }
        if (tid < 24) {
            int a = tid >> 3, i = tid & 7;
            const __half* src = (a == 0 ? gu : (a == 1 ? gv : gt)) + m0 + i * 8;
            __half2* dst = (a == 0 ? &U2s[s][0] : (a == 1 ? &V2s[s][0] : &T2s[s][0])) + i * 4;
            cp16(dst, src);
        }
        cp_commit();
    };

    issue(kb0, 0);
    uint2 awa = __ldg(&adjA[kb0]);
    uint2 awb = __ldg(&adjB[kb0]);

    for (int k2 = 0; k2 < ITER_PER; k2++) {
        int s = k2 & 1;
        cp_wait_all();
        __syncthreads();
        if (k2 + 1 < ITER_PER) issue(kb0 + k2 + 1, s ^ 1);
        uint2 nwa = make_uint2(0u, 0u), nwb = make_uint2(0u, 0u);
        if (k2 + 1 < ITER_PER) {
            nwa = __ldg(&adjA[kb0 + k2 + 1]);
            nwb = __ldg(&adjB[kb0 + k2 + 1]);
        }

        const char* HsB = (const char*)&Hs[s][0][0];
        #pragma unroll
        for (int kk = 0; kk < 4; kk++) {
            int p0 = kk * 8 + tc;
            int p1 = p0 + 4;
            uint32_t wa = (kk < 2) ? awa.x : awa.y;
            uint32_t wb = (kk < 2) ? awb.x : awb.y;
            int sh0 = (2 * p0) & 31;
            int sh1 = (2 * p1) & 31;

            __half2 u0 = U2s[s][p0], v0 = V2s[s][p0], t0 = T2s[s][p0];
            __half2 u1 = U2s[s][p1], v1 = V2s[s][p1], t1 = T2s[s][p1];

            uint32_t a[4];
            a[0] = pval(u0, v0, t0, Ea, nca, wa, sh0);
            a[1] = pval(u0, v0, t0, Eb, ncb, wb, sh0);
            a[2] = pval(u1, v1, t1, Ea, nca, wa, sh1);
            a[3] = pval(u1, v1, t1, Eb, ncb, wb, sh1);

            const char* rowB = HsB + (kk * 16 + (lane & 15)) * (HS_STRIDE * 2)
                                   + ((lane >> 4) * 8) * 2;
            // full N=80: 5 x4 transposed loads, mma immediately to limit live regs
            #pragma unroll
            for (int gg = 0; gg < 5; gg++) {
                uint32_t b0[2], b1[2];
                ldm_x4_t(b0[0], b0[1], b1[0], b1[1],
                         smem_u32(rowB + (gg * 16) * 2));
                mma16816(&acc[2 * gg][0], a, b0);
                mma16816(&acc[2 * gg + 1][0], a, b1);
            }
        }
        awa = nwa;
        awb = nwb;
    }

    // store unnormalized partials (all 80 cols incl. denominator col 64)
    float* pb = g_part + ((size_t)(z * NH + head) * NROW) * 80;
    int row0 = n0 + wid * 16 + g;
    #pragma unroll
    for (int nt = 0; nt < 10; nt++) {
        int col = nt * 8 + 2 * tc;
        *(float2*)&pb[(size_t)row0 * 80 + col] = make_float2(acc[nt][0], acc[nt][1]);
        *(float2*)&pb[(size_t)(row0 + 8) * 80 + col] = make_float2(acc[nt][2], acc[nt][3]);
    }
}

// ---------------- K5: combine split-K partials + normalize + write out ----------------
__global__ __launch_bounds__(256) void k5_combine(float* __restrict__ out) {
    int head = blockIdx.y;
    int r = blockIdx.x * 64 + (threadIdx.x >> 2);
    int q = threadIdx.x & 3;
    const float* p0 = g_part + ((size_t)(0 * NH + head) * NROW + r) * 80;
    const float* p1 = g_part + ((size_t)(1 * NH + head) * NROW + r) * 80;
    float inv = 1.0f / (p0[64] + p1[64]);
    #pragma unroll
    for (int j = 0; j < 4; j++) {
        float4 a = *(const float4*)&p0[q * 16 + j * 4];
        float4 b = *(const float4*)&p1[q * 16 + j * 4];
        float4 o;
        o.x = (a.x + b.x) * inv;
        o.y = (a.y + b.y) * inv;
        o.z = (a.z + b.z) * inv;
        o.w = (a.w + b.w) * inv;
        *(float4*)&out[(size_t)r * (NH * OD) + head * OD + q * 16 + j * 4] = o;
    }
}

// ---------------- launch ----------------
extern "C" void kernel_launch(void* const* d_in, const int* in_sizes, int n_in,
                              void* d_out, int out_size) {
    const float* x       = (const float*)d_in[0];
    const float* adj     = (const float*)d_in[1];
    const float* W       = (const float*)d_in[2];
    const float* a_self  = (const float*)d_in[3];
    const float* a_neigh = (const float*)d_in[4];
    float* out = (float*)d_out;

    kA        <<<NROW + 256, 256>>>(x, adj, W, a_self, a_neigh);
    k4_main   <<<dim3(NROW / RT, NH, KSPLIT), 128>>>();
    k5_combine<<<dim3(NROW / 64, NH), 256>>>(out);
}

// round 7
// speedup vs baseline: 1.7520x; 1.1136x over previous
#include <cuda_runtime.h>
#include <cuda_fp16.h>
#include <cstdint>

#define NROW 4096
#define IND  128
#define OD   64
#define NH   4
#define NC   80          // padded hv cols in gmem: 64 h | col64=1.0 | 65..79=0
#define NCOL 72          // cols actually used by k4 (64 h + denom + 0-pad to 72)
#define HS_STRIDE 88     // smem stride (halves), 16B*11 (odd) -> ldmatrix conflict-free
#define KC   64          // k-chunk (columns m per iteration)
#define RT   64          // row tile per block
#define KSPLIT 2
#define ITER_PER (NROW/KC/KSPLIT)   // 32
#define NW   (NROW/32)   // adj bit words per row = 128

// ---------------- scratch (static device globals; no cudaMalloc) ----------------
__device__ __half   g_hv[NH*NROW*NC];       // 2.6 MB  (h fp16 + ones col + pad)
__device__ __half   g_u[NH*NROW];           // e^t
__device__ __half   g_v[NH*NROW];           // e^{0.2 t}
__device__ __half   g_th[NH*NROW];          // t (half)
__device__ __half2  g_E2[NH*NROW];          // (e^{0.8c}, e^{0.8c})
__device__ __half2  g_nc[NH*NROW];          // (-c, -c)
__device__ uint32_t g_adjbits[NROW*NW];     // 2 MB bit-packed adjacency
__device__ float    g_part[KSPLIT*NH*NROW*80]; // 10.5 MB split-K partials

// ---------------- helpers ----------------
__device__ __forceinline__ uint32_t smem_u32(const void* p) {
    return (uint32_t)__cvta_generic_to_shared(p);
}
__device__ __forceinline__ void ldm_x4_t(uint32_t& r0, uint32_t& r1, uint32_t& r2, uint32_t& r3, uint32_t addr) {
    asm volatile("ldmatrix.sync.aligned.m8n8.x4.trans.shared.b16 {%0,%1,%2,%3}, [%4];"
                 : "=r"(r0), "=r"(r1), "=r"(r2), "=r"(r3) : "r"(addr));
}
__device__ __forceinline__ void ldm_x2_t(uint32_t& r0, uint32_t& r1, uint32_t addr) {
    asm volatile("ldmatrix.sync.aligned.m8n8.x2.trans.shared.b16 {%0,%1}, [%2];"
                 : "=r"(r0), "=r"(r1) : "r"(addr));
}
__device__ __forceinline__ void mma16816(float* c, const uint32_t* a, const uint32_t* b) {
    asm volatile("mma.sync.aligned.m16n8k16.row.col.f32.f16.f16.f32 "
                 "{%0,%1,%2,%3}, {%4,%5,%6,%7}, {%8,%9}, {%0,%1,%2,%3};"
                 : "+f"(c[0]), "+f"(c[1]), "+f"(c[2]), "+f"(c[3])
                 : "r"(a[0]), "r"(a[1]), "r"(a[2]), "r"(a[3]), "r"(b[0]), "r"(b[1]));
}
__device__ __forceinline__ void cp16(void* smem_dst, const void* gmem_src) {
    asm volatile("cp.async.cg.shared.global [%0], [%1], 16;"
                 :: "r"(smem_u32(smem_dst)), "l"(gmem_src));
}
__device__ __forceinline__ void cp_commit() {
    asm volatile("cp.async.commit_group;");
}
__device__ __forceinline__ void cp_wait1() {
    asm volatile("cp.async.wait_group 1;");
}

// P value for one (row, column-pair), with the e^{0.2c} row factor divided out:
//   P = adj ? (t > -c ? e^{0.8c} * e^t : e^{0.2t}) : 0
__device__ __forceinline__ uint32_t pval(__half2 u, __half2 v, __half2 t,
                                         __half2 E, __half2 nc,
                                         uint32_t w, int sh) {
    __half2 pos = __hmul2(u, E);
    uint32_t cm = __hgt2_mask(t, nc);
    uint32_t r = ((*(uint32_t*)&pos) & cm) | ((*(uint32_t*)&v) & ~cm);
    uint32_t b2 = (w >> sh) & 3u;
    uint32_t am = ((b2 & 1u) ? 0x0000FFFFu : 0u) | ((b2 & 2u) ? 0xFFFF0000u : 0u);
    return r & am;
}

// ---------------- KA: proj/scores blocks first, then smem-free adjacency pack ----------------
// blocks [0, 256):           projection tiles (64 rows x head) + per-row score exps
// blocks [256, 256+2048):    adjacency pack, 2 rows/block, per-thread 32-float pack
__global__ __launch_bounds__(256) void kA(const float* __restrict__ x,
                                          const float* __restrict__ adj,
                                          const float* __restrict__ W,
                                          const float* __restrict__ a_self,
                                          const float* __restrict__ a_neigh) {
    __shared__ float xs[64][33];   // 8.4 KB
    __shared__ float ws[32][68];   // 8.7 KB
    int bid = blockIdx.x;
    int tid = threadIdx.x;

    if (bid >= 256) {
        // ---- adjacency bit-pack: 2 rows per block, no smem, no sync ----
        int row = (bid - 256) * 2 + (tid >> 7);
        int w = tid & 127;
        const float4* p = (const float4*)(adj + (size_t)row * NROW + w * 32);
        float4 v[8];
        #pragma unroll
        for (int j = 0; j < 8; j++) v[j] = p[j];
        uint32_t bits = 0;
        #pragma unroll
        for (int j = 0; j < 8; j++) {
            bits |= ((v[j].x != 0.0f) ? 1u : 0u) << (4 * j);
            bits |= ((v[j].y != 0.0f) ? 2u : 0u) << (4 * j);
            bits |= ((v[j].z != 0.0f) ? 4u : 0u) << (4 * j);
            bits |= ((v[j].w != 0.0f) ? 8u : 0u) << (4 * j);
        }
        g_adjbits[row * NW + w] = bits;
        return;
    }

    // ---- projection tile: 64 rows x 64 cols for one head, k-chunks of 32 ----
    int head = bid >> 6;
    int r0 = (bid & 63) * 64;
    int tx = tid & 15, ty = tid >> 4;
    float acc[4][4] = {};
    for (int k0 = 0; k0 < IND; k0 += 32) {
        for (int idx = tid; idx < 64 * 32; idx += 256) {
            int r = idx >> 5, c = idx & 31;
            xs[r][c] = x[(r0 + r) * IND + k0 + c];
        }
        for (int idx = tid; idx < 32 * 64; idx += 256) {
            int r = idx >> 6, c = idx & 63;
            ws[r][c] = W[head * IND * OD + (k0 + r) * OD + c];
        }
        __syncthreads();
        for (int k = 0; k < 32; k++) {
            float4 wv = *(const float4*)&ws[k][tx * 4];
            #pragma unroll
            for (int i = 0; i < 4; i++) {
                float xv = xs[ty + 16 * i][k];
                acc[i][0] += xv * wv.x;
                acc[i][1] += xv * wv.y;
                acc[i][2] += xv * wv.z;
                acc[i][3] += xv * wv.w;
            }
        }
        __syncthreads();
    }
    // hv (fp16) + pad cols
    #pragma unroll
    for (int i = 0; i < 4; i++)
        #pragma unroll
        for (int j = 0; j < 4; j++) {
            int r = r0 + ty + 16 * i, c = tx * 4 + j;
            g_hv[(head * NROW + r) * NC + c] = __float2half(acc[i][j]);
        }
    for (int idx = tid; idx < 64 * 16; idx += 256) {
        int r = idx >> 4, pc = idx & 15;
        g_hv[(head * NROW + r0 + r) * NC + 64 + pc] =
            (pc == 0) ? __float2half(1.0f) : __float2half(0.0f);
    }
    // score dot partials (reuse xs as scratch: 2048 floats; xs has 2112)
    float as[4], an[4];
    #pragma unroll
    for (int j = 0; j < 4; j++) {
        as[j] = __ldg(&a_self[head * OD + tx * 4 + j]);
        an[j] = __ldg(&a_neigh[head * OD + tx * 4 + j]);
    }
    float* sp = &xs[0][0];
    #pragma unroll
    for (int i = 0; i < 4; i++) {
        float ps = 0.f, pn = 0.f;
        #pragma unroll
        for (int j = 0; j < 4; j++) { ps += acc[i][j] * as[j]; pn += acc[i][j] * an[j]; }
        int row = ty + 16 * i;
        sp[row * 16 + tx] = ps;
        sp[1024 + row * 16 + tx] = pn;
    }
    __syncthreads();
    if (tid < 64) {
        float c = 0.f, t = 0.f;
        #pragma unroll
        for (int xq = 0; xq < 16; xq++) {
            c += sp[tid * 16 + xq];
            t += sp[1024 + tid * 16 + xq];
        }
        int i = head * NROW + r0 + tid;
        g_u[i]  = __float2half(expf(t));
        g_v[i]  = __float2half(expf(0.2f * t));
        g_th[i] = __float2half(t);
        g_E2[i] = __float2half2_rn(expf(0.8f * c));
        g_nc[i] = __float2half2_rn(-c);
    }
}

// ---------------- K4: split-K, 1 warp per 16-row m-tile, N=72, 3-stage cp.async ring ----------------
__global__ __launch_bounds__(128, 5) void k4_main() {
    __shared__ __align__(16) __half  Hs[3][KC][HS_STRIDE];
    __shared__ __align__(16) __half2 U2s[3][KC/2];
    __shared__ __align__(16) __half2 V2s[3][KC/2];
    __shared__ __align__(16) __half2 T2s[3][KC/2];

    int head = blockIdx.y;
    int n0 = blockIdx.x * RT;
    int z = blockIdx.z;                  // k-split index
    int kb0 = z * ITER_PER;
    int tid = threadIdx.x;
    int lane = tid & 31, wid = tid >> 5; // wid = m-tile 0..3
    int g = lane >> 2, tc = lane & 3;

    int ra = n0 + wid * 16 + g;
    int rb = ra + 8;
    int ia = head * NROW + ra, ib = head * NROW + rb;
    __half2 Ea = g_E2[ia], nca = g_nc[ia];
    __half2 Eb = g_E2[ib], ncb = g_nc[ib];
    const uint2* adjA = (const uint2*)&g_adjbits[ra * NW];  // [kb] -> 64 cols
    const uint2* adjB = (const uint2*)&g_adjbits[rb * NW];

    float acc[9][4];
    #pragma unroll
    for (int b = 0; b < 9; b++)
        #pragma unroll
        for (int c = 0; c < 4; c++) acc[b][c] = 0.0f;

    const float4* hv4 = (const float4*)&g_hv[head * NROW * NC];
    const __half* gu = g_u + head * NROW;
    const __half* gv = g_v + head * NROW;
    const __half* gt = g_th + head * NROW;

    int kbEnd = kb0 + ITER_PER;
    auto issue = [&](int kbg, int s) {
        if (kbg < kbEnd) {
            int m0 = kbg * KC;
            #pragma unroll
            for (int i = 0; i < 5; i++) {
                int idx = tid + i * 128;
                if (idx < 64 * 9) {
                    int r = idx / 9, cg = idx - r * 9;
                    cp16(((char*)&Hs[s][r][0]) + cg * 16, (const char*)(hv4 + (m0 + r) * 10 + cg));
                }
            }
            if (tid < 24) {
                int a = tid >> 3, i = tid & 7;
                const __half* src = (a == 0 ? gu : (a == 1 ? gv : gt)) + m0 + i * 8;
                __half2* dst = (a == 0 ? &U2s[s][0] : (a == 1 ? &V2s[s][0] : &T2s[s][0])) + i * 4;
                cp16(dst, src);
            }
        }
        cp_commit();   // commit unconditionally to keep group accounting aligned
    };

    issue(kb0, 0);
    issue(kb0 + 1, 1);
    uint2 awa = __ldg(&adjA[kb0]);
    uint2 awb = __ldg(&adjB[kb0]);

    for (int k2 = 0; k2 < ITER_PER; k2++) {
        int s = k2 % 3;
        cp_wait1();            // stage k2 arrived (stage k2+1 may still be in flight)
        __syncthreads();       // all warps past compute of k2-1 -> stage (k2+2)%3 free
        issue(kb0 + k2 + 2, (k2 + 2) % 3);
        uint2 nwa = make_uint2(0u, 0u), nwb = make_uint2(0u, 0u);
        if (k2 + 1 < ITER_PER) {
            nwa = __ldg(&adjA[kb0 + k2 + 1]);
            nwb = __ldg(&adjB[kb0 + k2 + 1]);
        }

        const char* HsB = (const char*)&Hs[s][0][0];
        #pragma unroll
        for (int kk = 0; kk < 4; kk++) {
            int p0 = kk * 8 + tc;
            int p1 = p0 + 4;
            uint32_t wa = (kk < 2) ? awa.x : awa.y;
            uint32_t wb = (kk < 2) ? awb.x : awb.y;
            int sh0 = (2 * p0) & 31;
            int sh1 = (2 * p1) & 31;

            __half2 u0 = U2s[s][p0], v0 = V2s[s][p0], t0 = T2s[s][p0];
            __half2 u1 = U2s[s][p1], v1 = V2s[s][p1], t1 = T2s[s][p1];

            uint32_t a[4];
            a[0] = pval(u0, v0, t0, Ea, nca, wa, sh0);
            a[1] = pval(u0, v0, t0, Eb, ncb, wb, sh0);
            a[2] = pval(u1, v1, t1, Ea, nca, wa, sh1);
            a[3] = pval(u1, v1, t1, Eb, ncb, wb, sh1);

            const char* rowK = HsB + (kk * 16 + (lane & 15)) * (HS_STRIDE * 2);
            const char* rowB = rowK + ((lane >> 4) * 8) * 2;
            // cols 0..63: 4 x4 transposed loads, mma immediately
            #pragma unroll
            for (int gg = 0; gg < 4; gg++) {
                uint32_t b0[2], b1[2];
                ldm_x4_t(b0[0], b0[1], b1[0], b1[1],
                         smem_u32(rowB + (gg * 16) * 2));
                mma16816(&acc[2 * gg][0], a, b0);
                mma16816(&acc[2 * gg + 1][0], a, b1);
            }
            // cols 64..71 (denominator col 64 + zero pad): one x2 load
            {
                uint32_t b2[2];
                ldm_x2_t(b2[0], b2[1], smem_u32(rowK + 64 * 2));
                mma16816(&acc[8][0], a, b2);
            }
        }
        awa = nwa;
        awb = nwb;
    }

    // store unnormalized partials (cols 0..71 incl. denominator col 64)
    float* pb = g_part + ((size_t)(z * NH + head) * NROW) * 80;
    int row0 = n0 + wid * 16 + g;
    #pragma unroll
    for (int nt = 0; nt < 9; nt++) {
        int col = nt * 8 + 2 * tc;
        *(float2*)&pb[(size_t)row0 * 80 + col] = make_float2(acc[nt][0], acc[nt][1]);
        *(float2*)&pb[(size_t)(row0 + 8) * 80 + col] = make_float2(acc[nt][2], acc[nt][3]);
    }
}

// ---------------- K5: combine split-K partials + normalize + write out ----------------
__global__ __launch_bounds__(256) void k5_combine(float* __restrict__ out) {
    int head = blockIdx.y;
    int r = blockIdx.x * 64 + (threadIdx.x >> 2);
    int q = threadIdx.x & 3;
    const float* p0 = g_part + ((size_t)(0 * NH + head) * NROW + r) * 80;
    const float* p1 = g_part + ((size_t)(1 * NH + head) * NROW + r) * 80;
    float inv = 1.0f / (p0[64] + p1[64]);
    #pragma unroll
    for (int j = 0; j < 4; j++) {
        float4 a = *(const float4*)&p0[q * 16 + j * 4];
        float4 b = *(const float4*)&p1[q * 16 + j * 4];
        float4 o;
        o.x = (a.x + b.x) * inv;
        o.y = (a.y + b.y) * inv;
        o.z = (a.z + b.z) * inv;
        o.w = (a.w + b.w) * inv;
        *(float4*)&out[(size_t)r * (NH * OD) + head * OD + q * 16 + j * 4] = o;
    }
}

// ---------------- launch ----------------
extern "C" void kernel_launch(void* const* d_in, const int* in_sizes, int n_in,
                              void* d_out, int out_size) {
    const float* x       = (const float*)d_in[0];
    const float* adj     = (const float*)d_in[1];
    const float* W       = (const float*)d_in[2];
    const float* a_self  = (const float*)d_in[3];
    const float* a_neigh = (const float*)d_in[4];
    float* out = (float*)d_out;

    kA        <<<256 + NROW / 2, 256>>>(x, adj, W, a_self, a_neigh);
    k4_main   <<<dim3(NROW / RT, NH, KSPLIT), 128>>>();
    k5_combine<<<dim3(NROW / 64, NH), 256>>>(out);
}

// round 8
// speedup vs baseline: 1.9556x; 1.1162x over previous
#include <cuda_runtime.h>
#include <cuda_fp16.h>
#include <cstdint>

#define NROW 4096
#define IND  128
#define OD   64
#define NH   4
#define NC   80          // padded hv cols in gmem: 64 h | col64=1.0 | 65..79=0
#define HS_STRIDE 88     // smem stride (halves)
#define KC   64          // k-chunk (columns m per iteration)
#define RT   64          // row tile per block
#define KSPLIT 4
#define ITER_PER (NROW/KC/KSPLIT)   // 16
#define NW   (NROW/32)   // adj bit words per row = 128

// ---------------- scratch (static device globals; no cudaMalloc) ----------------
__device__ __half   g_hv[NH*NROW*NC];       // 2.6 MB  (h fp16 + ones col + pad)
__device__ __half   g_u[NH*NROW];           // e^t      (PERMUTED within 64-chunks)
__device__ __half   g_v[NH*NROW];           // e^{0.2t} (PERMUTED)
__device__ __half   g_th[NH*NROW];          // t        (PERMUTED)
__device__ __half2  g_E2[NH*NROW];          // (e^{0.8c}, e^{0.8c})
__device__ __half2  g_nc[NH*NROW];          // (-c, -c)
__device__ uint32_t g_adjbits[NROW*NW];     // 2 MB bit-packed adjacency
__device__ float    g_part[KSPLIT*NH*NROW*80]; // 21 MB split-K partials

// ---------------- helpers ----------------
__device__ __forceinline__ uint32_t smem_u32(const void* p) {
    return (uint32_t)__cvta_generic_to_shared(p);
}
__device__ __forceinline__ void ldm_x4_t(uint32_t& r0, uint32_t& r1, uint32_t& r2, uint32_t& r3, uint32_t addr) {
    asm volatile("ldmatrix.sync.aligned.m8n8.x4.trans.shared.b16 {%0,%1,%2,%3}, [%4];"
                 : "=r"(r0), "=r"(r1), "=r"(r2), "=r"(r3) : "r"(addr));
}
__device__ __forceinline__ void ldm_x2_t(uint32_t& r0, uint32_t& r1, uint32_t addr) {
    asm volatile("ldmatrix.sync.aligned.m8n8.x2.trans.shared.b16 {%0,%1}, [%2];"
                 : "=r"(r0), "=r"(r1) : "r"(addr));
}
__device__ __forceinline__ void mma16816(float* c, const uint32_t* a, const uint32_t* b) {
    asm volatile("mma.sync.aligned.m16n8k16.row.col.f32.f16.f16.f32 "
                 "{%0,%1,%2,%3}, {%4,%5,%6,%7}, {%8,%9}, {%0,%1,%2,%3};"
                 : "+f"(c[0]), "+f"(c[1]), "+f"(c[2]), "+f"(c[3])
                 : "r"(a[0]), "r"(a[1]), "r"(a[2]), "r"(a[3]), "r"(b[0]), "r"(b[1]));
}
__device__ __forceinline__ void cp16(void* smem_dst, const void* gmem_src) {
    asm volatile("cp.async.cg.shared.global [%0], [%1], 16;"
                 :: "r"(smem_u32(smem_dst)), "l"(gmem_src));
}
__device__ __forceinline__ void cp_commit() {
    asm volatile("cp.async.commit_group;");
}
__device__ __forceinline__ void cp_wait1() {
    asm volatile("cp.async.wait_group 1;");
}

// spread 8 bits -> every 4th bit position (bit m -> bit 4m)
__device__ __forceinline__ uint32_t spread4(uint32_t x) {
    x = (x | (x << 12)) & 0x000F000Fu;
    x = (x | (x << 6))  & 0x03030303u;
    x = (x | (x << 3))  & 0x11111111u;
    return x;
}

// P value for one (row, column-pair), with the e^{0.2c} row factor divided out:
//   P = adj ? (t > -c ? e^{0.8c} * e^t : e^{0.2t}) : 0
__device__ __forceinline__ uint32_t pval(__half2 u, __half2 v, __half2 t,
                                         __half2 E, __half2 nc,
                                         uint32_t w, int sh) {
    __half2 pos = __hmul2(u, E);
    uint32_t cm = __hgt2_mask(t, nc);
    uint32_t r = ((*(uint32_t*)&pos) & cm) | ((*(uint32_t*)&v) & ~cm);
    uint32_t b2 = (w >> sh) & 3u;
    uint32_t am = ((b2 & 1u) ? 0x0000FFFFu : 0u) | ((b2 & 2u) ? 0xFFFF0000u : 0u);
    return r & am;
}

// ---------------- KA: proj/scores blocks first, then ballot-coalesced adjacency pack ----------------
// blocks [0, 256):           projection tiles (64 rows x head) + per-row score exps
// blocks [256, 256+4096):    adjacency pack, 1 row/block, coalesced + ballot
__global__ __launch_bounds__(256) void kA(const float* __restrict__ x,
                                          const float* __restrict__ adj,
                                          const float* __restrict__ W,
                                          const float* __restrict__ a_self,
                                          const float* __restrict__ a_neigh) {
    __shared__ float xs[64][33];   // 8.4 KB
    __shared__ float ws[32][68];   // 8.7 KB
    int bid = blockIdx.x;
    int tid = threadIdx.x;

    if (bid >= 256) {
        // ---- adjacency bit-pack: 1 row/block, coalesced float4 + ballot assembly ----
        int row = bid - 256;
        int w8 = tid >> 5, lane = tid & 31;          // warp 0..7 covers cols [w8*512, +512)
        const float4* p4 = (const float4*)(adj + (size_t)row * NROW);
        float4 v[4];
        #pragma unroll
        for (int st = 0; st < 4; st++)
            v[st] = p4[w8 * 128 + st * 32 + lane];   // coalesced: lane -> cols 4*lane..+3
        #pragma unroll
        for (int st = 0; st < 4; st++) {
            uint32_t b0 = __ballot_sync(0xffffffffu, v[st].x != 0.0f);
            uint32_t b1 = __ballot_sync(0xffffffffu, v[st].y != 0.0f);
            uint32_t b2 = __ballot_sync(0xffffffffu, v[st].z != 0.0f);
            uint32_t b3 = __ballot_sync(0xffffffffu, v[st].w != 0.0f);
            if (lane < 4) {
                uint32_t word = spread4((b0 >> (8 * lane)) & 0xFFu)
                              | (spread4((b1 >> (8 * lane)) & 0xFFu) << 1)
                              | (spread4((b2 >> (8 * lane)) & 0xFFu) << 2)
                              | (spread4((b3 >> (8 * lane)) & 0xFFu) << 3);
                g_adjbits[row * NW + w8 * 16 + st * 4 + lane] = word;
            }
        }
        return;
    }

    // ---- projection tile: 64 rows x 64 cols for one head, k-chunks of 32 ----
    int head = bid >> 6;
    int r0 = (bid & 63) * 64;
    int tx = tid & 15, ty = tid >> 4;
    float acc[4][4] = {};
    for (int k0 = 0; k0 < IND; k0 += 32) {
        for (int idx = tid; idx < 64 * 32; idx += 256) {
            int r = idx >> 5, c = idx & 31;
            xs[r][c] = x[(r0 + r) * IND + k0 + c];
        }
        for (int idx = tid; idx < 32 * 64; idx += 256) {
            int r = idx >> 6, c = idx & 63;
            ws[r][c] = W[head * IND * OD + (k0 + r) * OD + c];
        }
        __syncthreads();
        for (int k = 0; k < 32; k++) {
            float4 wv = *(const float4*)&ws[k][tx * 4];
            #pragma unroll
            for (int i = 0; i < 4; i++) {
                float xv = xs[ty + 16 * i][k];
                acc[i][0] += xv * wv.x;
                acc[i][1] += xv * wv.y;
                acc[i][2] += xv * wv.z;
                acc[i][3] += xv * wv.w;
            }
        }
        __syncthreads();
    }
    // hv (fp16) + pad cols
    #pragma unroll
    for (int i = 0; i < 4; i++)
        #pragma unroll
        for (int j = 0; j < 4; j++) {
            int r = r0 + ty + 16 * i, c = tx * 4 + j;
            g_hv[(head * NROW + r) * NC + c] = __float2half(acc[i][j]);
        }
    for (int idx = tid; idx < 64 * 16; idx += 256) {
        int r = idx >> 4, pc = idx & 15;
        g_hv[(head * NROW + r0 + r) * NC + 64 + pc] =
            (pc == 0) ? __float2half(1.0f) : __float2half(0.0f);
    }
    // score dot partials (reuse xs as scratch: 2048 floats; xs has 2112)
    float as[4], an[4];
    #pragma unroll
    for (int j = 0; j < 4; j++) {
        as[j] = __ldg(&a_self[head * OD + tx * 4 + j]);
        an[j] = __ldg(&a_neigh[head * OD + tx * 4 + j]);
    }
    float* sp = &xs[0][0];
    #pragma unroll
    for (int i = 0; i < 4; i++) {
        float ps = 0.f, pn = 0.f;
        #pragma unroll
        for (int j = 0; j < 4; j++) { ps += acc[i][j] * as[j]; pn += acc[i][j] * an[j]; }
        int row = ty + 16 * i;
        sp[row * 16 + tx] = ps;
        sp[1024 + row * 16 + tx] = pn;
    }
    __syncthreads();
    if (tid < 64) {
        float c = 0.f, t = 0.f;
        #pragma unroll
        for (int xq = 0; xq < 16; xq++) {
            c += sp[tid * 16 + xq];
            t += sp[1024 + tid * 16 + xq];
        }
        int i = head * NROW + r0 + tid;
        // u/v/th written PERMUTED within the 64-chunk so k4's per-thread pair
        // (p, p+4) lands adjacent: half2 p -> q = (p&3)*8 + (p>>2)
        int p = tid >> 1, lh = tid & 1;
        int q = ((p & 3) << 3) | (p >> 2);
        int ip = head * NROW + r0 + q * 2 + lh;
        g_u[ip]  = __float2half(expf(t));
        g_v[ip]  = __float2half(expf(0.2f * t));
        g_th[ip] = __float2half(t);
        g_E2[i] = __float2half2_rn(expf(0.8f * c));
        g_nc[i] = __float2half2_rn(-c);
    }
}

// ---------------- K4: split-K(4), 1 warp per 16-row m-tile, N=72, 3-stage cp.async ring ----------------
__global__ __launch_bounds__(128, 5) void k4_main() {
    __shared__ __align__(16) __half  Hs[3][KC][HS_STRIDE];
    __shared__ __align__(16) __half2 U2s[3][KC/2];
    __shared__ __align__(16) __half2 V2s[3][KC/2];
    __shared__ __align__(16) __half2 T2s[3][KC/2];

    int head = blockIdx.y;
    int n0 = blockIdx.x * RT;
    int z = blockIdx.z;                  // k-split index
    int kb0 = z * ITER_PER;
    int tid = threadIdx.x;
    int lane = tid & 31, wid = tid >> 5; // wid = m-tile 0..3
    int g = lane >> 2, tc = lane & 3;

    int ra = n0 + wid * 16 + g;
    int rb = ra + 8;
    int ia = head * NROW + ra, ib = head * NROW + rb;
    __half2 Ea = g_E2[ia], nca = g_nc[ia];
    __half2 Eb = g_E2[ib], ncb = g_nc[ib];
    const uint2* adjA = (const uint2*)&g_adjbits[ra * NW];  // [kb] -> 64 cols
    const uint2* adjB = (const uint2*)&g_adjbits[rb * NW];

    float acc[9][4];
    #pragma unroll
    for (int b = 0; b < 9; b++)
        #pragma unroll
        for (int c = 0; c < 4; c++) acc[b][c] = 0.0f;

    const float4* hv4 = (const float4*)&g_hv[head * NROW * NC];
    const __half* gu = g_u + head * NROW;
    const __half* gv = g_v + head * NROW;
    const __half* gt = g_th + head * NROW;

    int kbEnd = kb0 + ITER_PER;
    auto issue = [&](int kbg, int s) {
        if (kbg < kbEnd) {
            int m0 = kbg * KC;
            #pragma unroll
            for (int i = 0; i < 5; i++) {
                int idx = tid + i * 128;
                if (idx < 64 * 9) {
                    int r = idx / 9, cg = idx - r * 9;
                    cp16(((char*)&Hs[s][r][0]) + cg * 16, (const char*)(hv4 + (m0 + r) * 10 + cg));
                }
            }
            if (tid < 24) {
                int a = tid >> 3, i = tid & 7;
                const __half* src = (a == 0 ? gu : (a == 1 ? gv : gt)) + m0 + i * 8;
                __half2* dst = (a == 0 ? &U2s[s][0] : (a == 1 ? &V2s[s][0] : &T2s[s][0])) + i * 4;
                cp16(dst, src);
            }
        }
        cp_commit();   // commit unconditionally to keep group accounting aligned
    };

    issue(kb0, 0);
    issue(kb0 + 1, 1);
    uint2 awa = __ldg(&adjA[kb0]);
    uint2 awb = __ldg(&adjB[kb0]);

    for (int k2 = 0; k2 < ITER_PER; k2++) {
        int s = k2 % 3;
        cp_wait1();            // stage k2 arrived (stage k2+1 may still be in flight)
        __syncthreads();       // all warps past compute of k2-1 -> stage (k2+2)%3 free
        issue(kb0 + k2 + 2, (k2 + 2) % 3);
        uint2 nwa = make_uint2(0u, 0u), nwb = make_uint2(0u, 0u);
        if (k2 + 1 < ITER_PER) {
            nwa = __ldg(&adjA[kb0 + k2 + 1]);
            nwb = __ldg(&adjB[kb0 + k2 + 1]);
        }

        const char* HsB = (const char*)&Hs[s][0][0];
        int qb = tc * 8;      // permuted base for this thread's column pairs
        #pragma unroll
        for (int kk = 0; kk < 4; kk++) {
            int p0 = kk * 8 + tc;            // logical pair index (for adjacency bits)
            int p1 = p0 + 4;
            uint32_t wa = (kk < 2) ? awa.x : awa.y;
            uint32_t wb = (kk < 2) ? awb.x : awb.y;
            int sh0 = (2 * p0) & 31;
            int sh1 = (2 * p1) & 31;

            // permuted smem: pairs (p0, p1) adjacent -> single 64-bit LDS each
            float2 uf = *(const float2*)&U2s[s][qb + 2 * kk];
            float2 vf = *(const float2*)&V2s[s][qb + 2 * kk];
            float2 tf = *(const float2*)&T2s[s][qb + 2 * kk];
            __half2 u0 = ((const __half2*)&uf)[0], u1 = ((const __half2*)&uf)[1];
            __half2 v0 = ((const __half2*)&vf)[0], v1 = ((const __half2*)&vf)[1];
            __half2 t0 = ((const __half2*)&tf)[0], t1 = ((const __half2*)&tf)[1];

            uint32_t a[4];
            a[0] = pval(u0, v0, t0, Ea, nca, wa, sh0);
            a[1] = pval(u0, v0, t0, Eb, ncb, wb, sh0);
            a[2] = pval(u1, v1, t1, Ea, nca, wa, sh1);
            a[3] = pval(u1, v1, t1, Eb, ncb, wb, sh1);

            const char* rowK = HsB + (kk * 16 + (lane & 15)) * (HS_STRIDE * 2);
            const char* rowB = rowK + ((lane >> 4) * 8) * 2;
            // cols 0..63: 4 x4 transposed loads, mma immediately
            #pragma unroll
            for (int gg = 0; gg < 4; gg++) {
                uint32_t b0[2], b1[2];
                ldm_x4_t(b0[0], b0[1], b1[0], b1[1],
                         smem_u32(rowB + (gg * 16) * 2));
                mma16816(&acc[2 * gg][0], a, b0);
                mma16816(&acc[2 * gg + 1][0], a, b1);
            }
            // cols 64..71 (denominator col 64 + zero pad): one x2 load
            {
                uint32_t b2[2];
                ldm_x2_t(b2[0], b2[1], smem_u32(rowK + 64 * 2));
                mma16816(&acc[8][0], a, b2);
            }
        }
        awa = nwa;
        awb = nwb;
    }

    // store unnormalized partials (cols 0..71 incl. denominator col 64)
    float* pb = g_part + ((size_t)(z * NH + head) * NROW) * 80;
    int row0 = n0 + wid * 16 + g;
    #pragma unroll
    for (int nt = 0; nt < 9; nt++) {
        int col = nt * 8 + 2 * tc;
        *(float2*)&pb[(size_t)row0 * 80 + col] = make_float2(acc[nt][0], acc[nt][1]);
        *(float2*)&pb[(size_t)(row0 + 8) * 80 + col] = make_float2(acc[nt][2], acc[nt][3]);
    }
}

// ---------------- K5: combine split-K partials + normalize + write out ----------------
__global__ __launch_bounds__(256) void k5_combine(float* __restrict__ out) {
    int head = blockIdx.y;
    int r = blockIdx.x * 64 + (threadIdx.x >> 2);
    int q = threadIdx.x & 3;
    const float* p0 = g_part + ((size_t)(0 * NH + head) * NROW + r) * 80;
    const float* p1 = g_part + ((size_t)(1 * NH + head) * NROW + r) * 80;
    const float* p2 = g_part + ((size_t)(2 * NH + head) * NROW + r) * 80;
    const float* p3 = g_part + ((size_t)(3 * NH + head) * NROW + r) * 80;
    float inv = 1.0f / (p0[64] + p1[64] + p2[64] + p3[64]);
    #pragma unroll
    for (int j = 0; j < 4; j++) {
        float4 a = *(const float4*)&p0[q * 16 + j * 4];
        float4 b = *(const float4*)&p1[q * 16 + j * 4];
        float4 c = *(const float4*)&p2[q * 16 + j * 4];
        float4 d = *(const float4*)&p3[q * 16 + j * 4];
        float4 o;
        o.x = (a.x + b.x + c.x + d.x) * inv;
        o.y = (a.y + b.y + c.y + d.y) * inv;
        o.z = (a.z + b.z + c.z + d.z) * inv;
        o.w = (a.w + b.w + c.w + d.w) * inv;
        *(float4*)&out[(size_t)r * (NH * OD) + head * OD + q * 16 + j * 4] = o;
    }
}

// ---------------- launch ----------------
extern "C" void kernel_launch(void* const* d_in, const int* in_sizes, int n_in,
                              void* d_out, int out_size) {
    const float* x       = (const float*)d_in[0];
    const float* adj     = (const float*)d_in[1];
    const float* W       = (const float*)d_in[2];
    const float* a_self  = (const float*)d_in[3];
    const float* a_neigh = (const float*)d_in[4];
    float* out = (float*)d_out;

    kA        <<<256 + NROW, 256>>>(x, adj, W, a_self, a_neigh);
    k4_main   <<<dim3(NROW / RT, NH, KSPLIT), 128>>>();
    k5_combine<<<dim3(NROW / 64, NH), 256>>>(out);
}